// round 13
// baseline (speedup 1.0000x reference)
#include <cuda_runtime.h>
#include <cuda_fp16.h>
#include <cstdint>
#include <cmath>

#define BSZ   32
#define SEQ   128
#define HID   512
#define NGATE 1536
#define VOC   32000
#define NTOK  4096   /* BSZ*SEQ */

// ---------------- device scratch (no allocations allowed) ----------------
__device__ int      g_tok[NTOK];
__device__ float    g_xg[(size_t)NTOK * NGATE];    // [S][B][3H], b_ih folded in
__device__ __half   g_hs_h[(size_t)NTOK * HID];    // fp16 hidden states
__device__ __half   g_wout_h[(size_t)VOC * HID];   // fp16 W_out
__device__ float    g_h[2][BSZ * HID];             // ping-pong hidden state
__device__ unsigned g_arr[128 * 32];               // per-CTA arrival slots (128B apart)

__device__ __forceinline__ unsigned f2tf(float x) {
    unsigned r;
    asm("cvt.rna.tf32.f32 %0, %1;" : "=r"(r) : "f"(x));
    return r;
}
__device__ __forceinline__ uint32_t s2u(const void* p) {
    uint32_t a;
    asm("{ .reg .u64 t; cvta.to.shared.u64 t, %1; cvt.u32.u64 %0, t; }"
        : "=r"(a) : "l"(p));
    return a;
}
// packed fp32x2 FMA: d = a*b + d  (two exact fp32 FMAs in one instruction)
__device__ __forceinline__ void fma2(unsigned long long& d,
                                     unsigned long long a,
                                     unsigned long long b) {
    asm("fma.rn.f32x2 %0, %1, %2, %0;" : "+l"(d) : "l"(a), "l"(b));
}
__device__ __forceinline__ float pairsum(unsigned long long v) {
    unsigned lo, hi;
    asm("mov.b64 {%0, %1}, %2;" : "=r"(lo), "=r"(hi) : "l"(v));
    return __uint_as_float(lo) + __uint_as_float(hi);
}

// targets may be int32 (JAX x64 disabled) or int64. Detect: int64 tokens
// always have zero high words -> first 8 int64 views all in [0, VOC).
__device__ __forceinline__ bool tok_is64(const void* p) {
    const long long* q = (const long long*)p;
    bool ok = true;
#pragma unroll
    for (int i = 0; i < 8; ++i) {
        long long v = q[i];
        ok = ok && (v >= 0) && (v < VOC);
    }
    return ok;
}
__device__ __forceinline__ int tok_at(const void* p, int idx, bool is64) {
    return is64 ? (int)((const long long*)p)[idx] : ((const int*)p)[idx];
}

__device__ __forceinline__ float fsigm(float x) {
    return __fdividef(1.f, 1.f + __expf(-x));
}
__device__ __forceinline__ float ftanh(float x) {
    float ax = fabsf(x);
    float e  = __expf(-2.f * ax);
    float t  = __fdividef(1.f - e, 1.f + e);
    return copysignf(t, x);
}

__device__ __forceinline__ void mma8(float* c, const uint32_t* a,
                                     uint32_t b0, uint32_t b1) {
    asm volatile(
        "mma.sync.aligned.m16n8k8.row.col.f32.tf32.tf32.f32 "
        "{%0,%1,%2,%3}, {%4,%5,%6,%7}, {%8,%9}, {%0,%1,%2,%3};"
        : "+f"(c[0]), "+f"(c[1]), "+f"(c[2]), "+f"(c[3])
        : "r"(a[0]), "r"(a[1]), "r"(a[2]), "r"(a[3]), "r"(b0), "r"(b1));
}
__device__ __forceinline__ void mma16h(float* c, uint32_t a0, uint32_t a1,
                                       uint32_t a2, uint32_t a3,
                                       uint32_t b0, uint32_t b1) {
    asm volatile(
        "mma.sync.aligned.m16n8k16.row.col.f32.f16.f16.f32 "
        "{%0,%1,%2,%3}, {%4,%5,%6,%7}, {%8,%9}, {%0,%1,%2,%3};"
        : "+f"(c[0]), "+f"(c[1]), "+f"(c[2]), "+f"(c[3])
        : "r"(a0), "r"(a1), "r"(a2), "r"(a3), "r"(b0), "r"(b1));
}

// ---------------- init: token indices, h0, barrier reset -----------------
__global__ void init_kernel(const void* __restrict__ targets,
                            const int* __restrict__ init_tok,
                            const float* __restrict__ hidden) {
    const bool is64 = tok_is64(targets);
    int t = blockIdx.x * blockDim.x + threadIdx.x;
    int nt = gridDim.x * blockDim.x;
    for (int i = t; i < 128 * 32; i += nt) g_arr[i] = 0u;
    if (t < NTOK) {
        int s = t >> 5, b = t & 31;
        g_tok[t] = (s == 0) ? init_tok[0]
                            : tok_at(targets, b * SEQ + (s - 1), is64);
    }
    for (int i = t; i < BSZ * HID; i += nt)
        g_h[0][i] = hidden[i];
}

// ---------------- pre-convert W_out to fp16 (RN) -------------------------
__global__ void conv_w(const float* __restrict__ W) {
    int t = blockIdx.x * blockDim.x + threadIdx.x;
    int nt = gridDim.x * blockDim.x;
    const int n4 = (VOC * HID) / 4;
    for (int i = t; i < n4; i += nt) {
        float4 v = ((const float4*)W)[i];
        __half2 h01 = __floats2half2_rn(v.x, v.y);
        __half2 h23 = __floats2half2_rn(v.z, v.w);
        *(__half2*)(g_wout_h + (size_t)i * 4)     = h01;
        *(__half2*)(g_wout_h + (size_t)i * 4 + 2) = h23;
    }
}

// ---------------- x_gates GEMM (embedding gather, tf32 mma.sync) ---------
__global__ void __launch_bounds__(256, 2)
gemm_xg(const float* __restrict__ A, const float* __restrict__ Bm,
        const float* __restrict__ bias) {
    __shared__ unsigned As[128 * 36];
    __shared__ unsigned Bs[128 * 36];

    const int tid  = threadIdx.x;
    const int n0   = blockIdx.x * 128;
    const int m0   = blockIdx.y * 128;
    const int lane = tid & 31, warp = tid >> 5;
    const int wm = warp & 1, wn = warp >> 1;
    const int g  = lane >> 2, tg = lane & 3;

    const float* aptr[4];
    const float* bptr[4];
    int soff[4];
#pragma unroll
    for (int i = 0; i < 4; ++i) {
        int idx = tid + i * 256;
        int row = idx >> 3, cv = idx & 7;
        int arow = g_tok[m0 + row];
        aptr[i] = A + (size_t)arow * HID + cv * 4;
        bptr[i] = Bm + (size_t)(n0 + row) * HID + cv * 4;
        soff[i] = row * 36 + cv * 4;
    }

    float c[4][4][4];
#pragma unroll
    for (int a = 0; a < 4; ++a)
#pragma unroll
        for (int b = 0; b < 4; ++b)
#pragma unroll
            for (int k = 0; k < 4; ++k) c[a][b][k] = 0.f;

    for (int kt = 0; kt < 16; ++kt) {
        float4 va[4], vb[4];
#pragma unroll
        for (int i = 0; i < 4; ++i) {
            va[i] = *(const float4*)(aptr[i] + kt * 32);
            vb[i] = *(const float4*)(bptr[i] + kt * 32);
        }
        __syncthreads();
#pragma unroll
        for (int i = 0; i < 4; ++i) {
            As[soff[i] + 0] = f2tf(va[i].x); As[soff[i] + 1] = f2tf(va[i].y);
            As[soff[i] + 2] = f2tf(va[i].z); As[soff[i] + 3] = f2tf(va[i].w);
            Bs[soff[i] + 0] = f2tf(vb[i].x); Bs[soff[i] + 1] = f2tf(vb[i].y);
            Bs[soff[i] + 2] = f2tf(vb[i].z); Bs[soff[i] + 3] = f2tf(vb[i].w);
        }
        __syncthreads();

#pragma unroll
        for (int kk = 0; kk < 4; ++kk) {
            const int kb = kk * 8;
            unsigned afr[4][4], bfr[4][2];
#pragma unroll
            for (int mf = 0; mf < 4; ++mf) {
                int r0 = (wm * 64 + mf * 16 + g) * 36 + kb + tg;
                afr[mf][0] = As[r0];
                afr[mf][1] = As[r0 + 8 * 36];
                afr[mf][2] = As[r0 + 4];
                afr[mf][3] = As[r0 + 8 * 36 + 4];
            }
#pragma unroll
            for (int nf = 0; nf < 4; ++nf) {
                int r0 = (wn * 32 + nf * 8 + g) * 36 + kb + tg;
                bfr[nf][0] = Bs[r0];
                bfr[nf][1] = Bs[r0 + 4];
            }
#pragma unroll
            for (int mf = 0; mf < 4; ++mf)
#pragma unroll
                for (int nf = 0; nf < 4; ++nf)
                    mma8(c[mf][nf], afr[mf], bfr[nf][0], bfr[nf][1]);
        }
    }

#pragma unroll
    for (int mf = 0; mf < 4; ++mf) {
#pragma unroll
        for (int nf = 0; nf < 4; ++nf) {
            int row = m0 + wm * 64 + mf * 16 + g;
            int col = n0 + wn * 32 + nf * 8 + 2 * tg;
            float b0v = bias[col], b1v = bias[col + 1];
            float2 v0 = make_float2(c[mf][nf][0] + b0v, c[mf][nf][1] + b1v);
            float2 v1 = make_float2(c[mf][nf][2] + b0v, c[mf][nf][3] + b1v);
            *(float2*)&g_xg[(size_t)row * NGATE + col]       = v0;
            *(float2*)&g_xg[(size_t)(row + 8) * NGATE + col] = v1;
        }
    }
}

// ---------------- logits GEMM: fp16 m16n8k16, small-stage cp.async -------
// K chunk = 16 halves (32B rows, zero pad: words mod 32 = (g%4)*8+tg*2 is
// conflict-free). 3 stages x 8KB = 24.6KB total so recur(116.4KB)+gemm3
// (24.6KB) = 141KB sits well inside the proven co-residency envelope
// (157.3KB worked in R10, 165.6KB failed) -> gemm3 co-resides with scan.
#define GKH   16            /* halves per chunk */
#define NCHH  32            /* 512 / 16 */
#define RSB   32            /* bytes per row in smem */
#define AWB   (128 * RSB)   /* 4096 B per A stage */
#define STWB  (2 * AWB)     /* 8192 B per stage */
#define SMEMH (3 * STWB)    /* 24576 B */

__global__ void __launch_bounds__(256, 2)
gemm3(const float* __restrict__ bias, float* __restrict__ out) {
    // ---- PDL gate: wait until the scan has produced this tile's rows ----
    {
        const unsigned need = (unsigned)(blockIdx.y * 4 + 4);
        if (threadIdx.x < 32) {
            for (;;) {
                unsigned ok = 1;
#pragma unroll
                for (int i = 0; i < 4; ++i) {
                    unsigned v;
                    asm volatile("ld.acquire.gpu.global.u32 %0, [%1];"
                                 : "=r"(v)
                                 : "l"(&g_arr[(threadIdx.x * 4 + i) * 32])
                                 : "memory");
                    ok &= (v >= need) ? 1u : 0u;
                }
                if (__all_sync(0xffffffffu, ok)) break;
                __nanosleep(256);
            }
        }
        __syncthreads();
    }

    extern __shared__ char smemc[];
    const uint32_t sb = s2u(smemc);
    const int tid  = threadIdx.x;
    const int wid  = tid >> 5, lane = tid & 31;
    const int wm = wid & 1, wn = wid >> 1;         // 2 x 4 warps
    const int g  = lane >> 2, tg = lane & 3;
    const int n0 = blockIdx.x * 128, m0 = blockIdx.y * 128;

    // one 16B cp.async per thread per operand per chunk (256 slots each)
    const int r_ld = tid >> 1, hf_ld = tid & 1;
    const __half* asrc = g_hs_h  + (size_t)(m0 + r_ld) * HID + hf_ld * 8;
    const __half* bsrc = g_wout_h + (size_t)(n0 + r_ld) * HID + hf_ld * 8;
    const uint32_t adst = (uint32_t)(r_ld * RSB + hf_ld * 16);
    const uint32_t bdst = (uint32_t)(AWB + r_ld * RSB + hf_ld * 16);

    float c[4][4][4];
#pragma unroll
    for (int mf = 0; mf < 4; ++mf)
#pragma unroll
        for (int nf = 0; nf < 4; ++nf)
#pragma unroll
            for (int k = 0; k < 4; ++k) c[mf][nf][k] = 0.f;

#pragma unroll
    for (int pc = 0; pc < 2; ++pc) {      // prologue: chunks 0,1
        uint32_t sbase = sb + (uint32_t)(pc * STWB);
        int kb = pc * GKH;
        asm volatile("cp.async.cg.shared.global [%0], [%1], 16;"
                     :: "r"(sbase + adst), "l"(asrc + kb) : "memory");
        asm volatile("cp.async.cg.shared.global [%0], [%1], 16;"
                     :: "r"(sbase + bdst), "l"(bsrc + kb) : "memory");
        asm volatile("cp.async.commit_group;" ::: "memory");
    }

#pragma unroll 1
    for (int ch = 0; ch < NCHH; ++ch) {
        asm volatile("cp.async.wait_group 1;" ::: "memory");  // chunk ch done
        __syncthreads();   // all warps done reading stage (ch+2)%3 (iter ch-1)

        {   // issue chunk ch+2 into stage (ch+2)%3
            int nc = ch + 2;
            if (nc < NCHH) {
                uint32_t sbase = sb + (uint32_t)((nc % 3) * STWB);
                int kb = nc * GKH;
                asm volatile("cp.async.cg.shared.global [%0], [%1], 16;"
                             :: "r"(sbase + adst), "l"(asrc + kb) : "memory");
                asm volatile("cp.async.cg.shared.global [%0], [%1], 16;"
                             :: "r"(sbase + bdst), "l"(bsrc + kb) : "memory");
            }
            asm volatile("cp.async.commit_group;" ::: "memory");
        }

        const uint32_t sbase = sb + (uint32_t)((ch % 3) * STWB);
        uint32_t a[4][4];
#pragma unroll
        for (int mf = 0; mf < 4; ++mf) {
            int r0 = wm * 64 + mf * 16 + g;
            uint32_t ad0 = sbase + (uint32_t)(r0 * RSB + tg * 8);
            uint32_t ad1 = sbase + (uint32_t)((r0 + 8) * RSB + tg * 8);
            asm volatile("ld.shared.v2.b32 {%0,%1}, [%2];"
                         : "=r"(a[mf][0]), "=r"(a[mf][2]) : "r"(ad0));
            asm volatile("ld.shared.v2.b32 {%0,%1}, [%2];"
                         : "=r"(a[mf][1]), "=r"(a[mf][3]) : "r"(ad1));
        }
#pragma unroll
        for (int nf = 0; nf < 4; ++nf) {
            int rn = wn * 32 + nf * 8 + g;
            uint32_t bd = sbase + (uint32_t)(AWB + rn * RSB + tg * 8);
            uint32_t b0, b1;
            asm volatile("ld.shared.v2.b32 {%0,%1}, [%2];"
                         : "=r"(b0), "=r"(b1) : "r"(bd));
#pragma unroll
            for (int mf = 0; mf < 4; ++mf)
                mma16h(c[mf][nf], a[mf][0], a[mf][1], a[mf][2], a[mf][3],
                       b0, b1);
        }
    }

    // epilogue: rows -> (s,b) remap, add bias
#pragma unroll
    for (int mf = 0; mf < 4; ++mf) {
        int row = m0 + wm * 64 + mf * 16 + g;
        int s0 = row >> 5, b0i = row & 31;
        int r1 = row + 8;
        int s1 = r1 >> 5, b1i = r1 & 31;
        float* o0 = out + ((size_t)b0i * SEQ + s0) * VOC;
        float* o1 = out + ((size_t)b1i * SEQ + s1) * VOC;
#pragma unroll
        for (int nf = 0; nf < 4; ++nf) {
            int col = n0 + wn * 32 + nf * 8 + 2 * tg;
            float bv0 = bias[col], bv1 = bias[col + 1];
            *(float2*)(o0 + col) = make_float2(c[mf][nf][0] + bv0,
                                               c[mf][nf][1] + bv1);
            *(float2*)(o1 + col) = make_float2(c[mf][nf][2] + bv0,
                                               c[mf][nf][3] + bv1);
        }
    }
}

// ---------------- persistent GRU scan: 32 j-groups x 4 batch-groups ------
// (unchanged from R11/R12: 568us, bit-identical outputs)
#define RS_H   0
#define RS_W   4096
#define RS_BI  (RS_W + 48 * HID)
#define RS_XG  (RS_BI + 48)
#define RS_TOT ((RS_XG + 384) * 4)     /* 116416 B */

__global__ void __launch_bounds__(256, 2)
recur_kernel(const float* __restrict__ W_hh, const float* __restrict__ b_hh) {
    // allow the dependent logits GEMM to start launching now
    asm volatile("griddepcontrol.launch_dependents;" ::: "memory");

    extern __shared__ float sm[];
    float* h_sm    = sm + RS_H;
    float* w_sm    = sm + RS_W;
    float* bias_sm = sm + RS_BI;
    float* xg_sm   = sm + RS_XG;
    const uint32_t sb = s2u(sm);

    const int tid = threadIdx.x;
    const int bg  = blockIdx.x & 3;
    const int jg  = blockIdx.x >> 2;
    const int j0  = jg * 16;
    const int bbase = bg * 8;

    // load W slice: 48 rows (16 local j x 3 gates) x 512
    for (int i = tid; i < 48 * HID; i += 256) {
        int r = i >> 9, k = i & 511;
        int lj = r / 3, gg = r % 3;
        w_sm[i] = W_hh[(size_t)(gg * HID + j0 + lj) * HID + k];
    }
    if (tid < 48) {
        int lj = tid / 3, gg = tid % 3;
        bias_sm[tid] = b_hh[gg * HID + j0 + lj];
    }

    const int ks = tid & 15;          // 16-way k split
    const int grp = tid >> 4;         // 16 (bq, jl) groups
    const int bq = grp & 1;           // 2 batch quads (4 b each)
    const int jl = grp >> 1;          // 8 j-pairs: lj = jl*2 + jj
    const float* wp[6];               // [jj*3 + gate]
#pragma unroll
    for (int jj = 0; jj < 2; ++jj)
#pragma unroll
        for (int gg = 0; gg < 3; ++gg)
            wp[jj * 3 + gg] = w_sm + ((jl * 2 + jj) * 3 + gg) * HID;

    // xg staging (tid < 96): 8 b x 3 gates x 4 quarters of 4 j
    const int xbl = tid / 12, xrem = tid - xbl * 12;
    const int xgt = xrem >> 2, xq = xrem & 3;
    const uint32_t xg_dst =
        sb + (uint32_t)((RS_XG + xbl * 48 + xgt * 16 + xq * 4) * 4);
    const float* xg_srcb =
        g_xg + (size_t)(bbase + xbl) * NGATE + xgt * HID + j0 + xq * 4;

    __syncthreads();

    for (int s = 0; s < SEQ; ++s) {
        // stage xg[s] slice (independent of h)
        if (tid < 96) {
            const float* src = xg_srcb + (size_t)s * BSZ * NGATE;
            asm volatile("cp.async.cg.shared.global [%0], [%1], 16;"
                         :: "r"(xg_dst), "l"(src) : "memory");
        }
        // broadcast own batch column's h (8 x 512 = 16KB) into smem
        {
            const float* src = g_h[s & 1] + bbase * HID;
#pragma unroll
            for (int t = 0; t < 4; ++t) {
                int idx = tid + t * 256;
                asm volatile("cp.async.cg.shared.global [%0], [%1], 16;"
                             :: "r"(sb + (uint32_t)((RS_H + idx * 4) * 4)),
                                "l"(src + idx * 4) : "memory");
            }
        }
        asm volatile("cp.async.commit_group;" ::: "memory");
        asm volatile("cp.async.wait_group 0;" ::: "memory");
        __syncthreads();

        unsigned long long acc[6][4];   // [jj*3+gate][bi]
#pragma unroll
        for (int q = 0; q < 6; ++q)
#pragma unroll
            for (int bi = 0; bi < 4; ++bi) acc[q][bi] = 0ull;

#pragma unroll
        for (int i = 0; i < 8; ++i) {
            int k = ks * 4 + i * 64;
            ulonglong2 w2[6];
#pragma unroll
            for (int q = 0; q < 6; ++q)
                w2[q] = *(const ulonglong2*)(wp[q] + k);
#pragma unroll
            for (int bi = 0; bi < 4; ++bi) {
                int bl = bq * 4 + bi;
                ulonglong2 h2 = *(const ulonglong2*)(h_sm + bl * HID + k);
#pragma unroll
                for (int q = 0; q < 6; ++q) {
                    fma2(acc[q][bi], h2.x, w2[q].x);
                    fma2(acc[q][bi], h2.y, w2[q].y);
                }
            }
        }
        float a[6][4];
#pragma unroll
        for (int q = 0; q < 6; ++q)
#pragma unroll
            for (int bi = 0; bi < 4; ++bi) a[q][bi] = pairsum(acc[q][bi]);
        // reduce across the 16 k-split lanes
#pragma unroll
        for (int off = 8; off > 0; off >>= 1) {
#pragma unroll
            for (int q = 0; q < 6; ++q)
#pragma unroll
                for (int bi = 0; bi < 4; ++bi)
                    a[q][bi] += __shfl_xor_sync(0xffffffffu, a[q][bi], off);
        }
        if (ks == 0) {
#pragma unroll
            for (int jj = 0; jj < 2; ++jj) {
                int lj = jl * 2 + jj;
                int j  = j0 + lj;
                float br = bias_sm[lj * 3 + 0];
                float bz = bias_sm[lj * 3 + 1];
                float bn = bias_sm[lj * 3 + 2];
#pragma unroll
                for (int bi = 0; bi < 4; ++bi) {
                    int bl = bq * 4 + bi;
                    int b  = bbase + bl;
                    float rr = fsigm(xg_sm[bl * 48 + 0  + lj] + a[jj * 3 + 0][bi] + br);
                    float zz = fsigm(xg_sm[bl * 48 + 16 + lj] + a[jj * 3 + 1][bi] + bz);
                    float nn = ftanh(xg_sm[bl * 48 + 32 + lj] +
                                     rr * (a[jj * 3 + 2][bi] + bn));
                    float hold = h_sm[bl * HID + j];
                    float hnew = (1.f - zz) * nn + zz * hold;
                    g_h[(s + 1) & 1][b * HID + j] = hnew;
                    g_hs_h[(size_t)(s * BSZ + b) * HID + j] =
                        __float2half_rn(hnew);
                }
            }
        }
        if (s == SEQ - 1) break;

        // ---- column barrier: store-arrive + poll own 32 CTAs ----
        __syncthreads();
        const unsigned sv = (unsigned)(s + 1);
        if (tid == 0) {
            asm volatile("st.release.gpu.global.u32 [%0], %1;"
                         :: "l"(&g_arr[blockIdx.x * 32]), "r"(sv) : "memory");
        }
        if (tid < 32) {
            int cc = tid * 4 + bg;     // same-column CTA ids
            for (;;) {
                unsigned v;
                asm volatile("ld.acquire.gpu.global.u32 %0, [%1];"
                             : "=r"(v) : "l"(&g_arr[cc * 32]) : "memory");
                if (__all_sync(0xffffffffu, (v >= sv) ? 1u : 0u)) break;
            }
        }
        __syncthreads();
    }

    // final arrival: publish step 128 (releases last M-tiles to gemm3)
    __syncthreads();
    if (tid == 0) {
        asm volatile("st.release.gpu.global.u32 [%0], %1;"
                     :: "l"(&g_arr[blockIdx.x * 32]), "r"((unsigned)SEQ)
                     : "memory");
    }
}

// ---------------- launch ----------------
extern "C" void kernel_launch(void* const* d_in, const int* in_sizes, int n_in,
                              void* d_out, int out_size) {
    const float* hidden    = (const float*)d_in[0];
    const void*  targets   = (const void*)d_in[1];
    const float* embedding = (const float*)d_in[2];
    const float* W_ih      = (const float*)d_in[3];
    const float* W_hh      = (const float*)d_in[4];
    const float* b_ih      = (const float*)d_in[5];
    const float* b_hh      = (const float*)d_in[6];
    const float* W_out     = (const float*)d_in[7];
    const float* b_out     = (const float*)d_in[8];
    const int*   init_tok  = (const int*)d_in[9];
    float*       out       = (float*)d_out;

    cudaFuncSetAttribute(recur_kernel,
                         cudaFuncAttributeMaxDynamicSharedMemorySize, RS_TOT);
    cudaFuncSetAttribute(gemm3,
                         cudaFuncAttributeMaxDynamicSharedMemorySize, SMEMH);

    init_kernel<<<16, 256>>>(targets, init_tok, hidden);

    // x_gates: [4096 x 1536 x 512], A gathered from embedding
    gemm_xg<<<dim3(NGATE / 128, NTOK / 128), 256>>>(embedding, W_ih, b_ih);

    // pre-round W_out to fp16 (RN)
    conv_w<<<256, 256>>>(W_out);

    // sequential GRU scan (persistent, 128 co-resident CTAs)
    recur_kernel<<<128, 256, RS_TOT>>>(W_hh, b_hh);

    // logits GEMM (fp16, 24.6KB smem), PDL-overlapped with the scan
    {
        cudaLaunchConfig_t cfg = {};
        cfg.gridDim  = dim3(VOC / 128, NTOK / 128);
        cfg.blockDim = dim3(256);
        cfg.dynamicSmemBytes = SMEMH;
        cudaLaunchAttribute attr[1];
        attr[0].id = cudaLaunchAttributeProgrammaticStreamSerialization;
        attr[0].val.programmaticStreamSerializationAllowed = 1;
        cfg.attrs = attr;
        cfg.numAttrs = 1;
        cudaLaunchKernelEx(&cfg, gemm3, (const float*)b_out, out);
    }
}

// round 14
// speedup vs baseline: 1.1747x; 1.1747x over previous
#include <cuda_runtime.h>
#include <cuda_fp16.h>
#include <cstdint>
#include <cmath>

#define BSZ   32
#define SEQ   128
#define HID   512
#define NGATE 1536
#define VOC   32000
#define NTOK  4096   /* BSZ*SEQ */

// ---------------- device scratch (no allocations allowed) ----------------
__device__ int      g_tok[NTOK];
__device__ float    g_xg[(size_t)NTOK * NGATE];    // [S][B][3H], b_ih folded in
__device__ __half   g_hs_h[(size_t)NTOK * HID];    // fp16 hidden states
__device__ __half   g_wout_h[(size_t)VOC * HID];   // fp16 W_out
__device__ float    g_h[2][BSZ * HID];             // ping-pong hidden state
__device__ unsigned g_arr[128 * 32];               // per-CTA arrival slots (128B apart)

__device__ __forceinline__ unsigned f2tf(float x) {
    unsigned r;
    asm("cvt.rna.tf32.f32 %0, %1;" : "=r"(r) : "f"(x));
    return r;
}
__device__ __forceinline__ uint32_t s2u(const void* p) {
    uint32_t a;
    asm("{ .reg .u64 t; cvta.to.shared.u64 t, %1; cvt.u32.u64 %0, t; }"
        : "=r"(a) : "l"(p));
    return a;
}
// packed fp32x2 FMA: d = a*b + d  (two exact fp32 FMAs in one instruction)
__device__ __forceinline__ void fma2(unsigned long long& d,
                                     unsigned long long a,
                                     unsigned long long b) {
    asm("fma.rn.f32x2 %0, %1, %2, %0;" : "+l"(d) : "l"(a), "l"(b));
}
__device__ __forceinline__ float pairsum(unsigned long long v) {
    unsigned lo, hi;
    asm("mov.b64 {%0, %1}, %2;" : "=r"(lo), "=r"(hi) : "l"(v));
    return __uint_as_float(lo) + __uint_as_float(hi);
}

// targets may be int32 (JAX x64 disabled) or int64. Detect: int64 tokens
// always have zero high words -> first 8 int64 views all in [0, VOC).
__device__ __forceinline__ bool tok_is64(const void* p) {
    const long long* q = (const long long*)p;
    bool ok = true;
#pragma unroll
    for (int i = 0; i < 8; ++i) {
        long long v = q[i];
        ok = ok && (v >= 0) && (v < VOC);
    }
    return ok;
}
__device__ __forceinline__ int tok_at(const void* p, int idx, bool is64) {
    return is64 ? (int)((const long long*)p)[idx] : ((const int*)p)[idx];
}

__device__ __forceinline__ float fsigm(float x) {
    return __fdividef(1.f, 1.f + __expf(-x));
}
__device__ __forceinline__ float ftanh(float x) {
    float ax = fabsf(x);
    float e  = __expf(-2.f * ax);
    float t  = __fdividef(1.f - e, 1.f + e);
    return copysignf(t, x);
}

__device__ __forceinline__ void mma8(float* c, const uint32_t* a,
                                     uint32_t b0, uint32_t b1) {
    asm volatile(
        "mma.sync.aligned.m16n8k8.row.col.f32.tf32.tf32.f32 "
        "{%0,%1,%2,%3}, {%4,%5,%6,%7}, {%8,%9}, {%0,%1,%2,%3};"
        : "+f"(c[0]), "+f"(c[1]), "+f"(c[2]), "+f"(c[3])
        : "r"(a[0]), "r"(a[1]), "r"(a[2]), "r"(a[3]), "r"(b0), "r"(b1));
}
__device__ __forceinline__ void mma16h(float* c, uint32_t a0, uint32_t a1,
                                       uint32_t a2, uint32_t a3,
                                       uint32_t b0, uint32_t b1) {
    asm volatile(
        "mma.sync.aligned.m16n8k16.row.col.f32.f16.f16.f32 "
        "{%0,%1,%2,%3}, {%4,%5,%6,%7}, {%8,%9}, {%0,%1,%2,%3};"
        : "+f"(c[0]), "+f"(c[1]), "+f"(c[2]), "+f"(c[3])
        : "r"(a0), "r"(a1), "r"(a2), "r"(a3), "r"(b0), "r"(b1));
}

// ---------------- init: token indices, h0, barrier reset -----------------
__global__ void init_kernel(const void* __restrict__ targets,
                            const int* __restrict__ init_tok,
                            const float* __restrict__ hidden) {
    const bool is64 = tok_is64(targets);
    int t = blockIdx.x * blockDim.x + threadIdx.x;
    int nt = gridDim.x * blockDim.x;
    for (int i = t; i < 128 * 32; i += nt) g_arr[i] = 0u;
    if (t < NTOK) {
        int s = t >> 5, b = t & 31;
        g_tok[t] = (s == 0) ? init_tok[0]
                            : tok_at(targets, b * SEQ + (s - 1), is64);
    }
    for (int i = t; i < BSZ * HID; i += nt)
        g_h[0][i] = hidden[i];
}

// ---------------- pre-convert W_out to fp16 (RN) -------------------------
__global__ void conv_w(const float* __restrict__ W) {
    int t = blockIdx.x * blockDim.x + threadIdx.x;
    int nt = gridDim.x * blockDim.x;
    const int n4 = (VOC * HID) / 4;
    for (int i = t; i < n4; i += nt) {
        float4 v = ((const float4*)W)[i];
        __half2 h01 = __floats2half2_rn(v.x, v.y);
        __half2 h23 = __floats2half2_rn(v.z, v.w);
        *(__half2*)(g_wout_h + (size_t)i * 4)     = h01;
        *(__half2*)(g_wout_h + (size_t)i * 4 + 2) = h23;
    }
}

// ---------------- x_gates GEMM (embedding gather, tf32 mma.sync) ---------
__global__ void __launch_bounds__(256, 2)
gemm_xg(const float* __restrict__ A, const float* __restrict__ Bm,
        const float* __restrict__ bias) {
    __shared__ unsigned As[128 * 36];
    __shared__ unsigned Bs[128 * 36];

    const int tid  = threadIdx.x;
    const int n0   = blockIdx.x * 128;
    const int m0   = blockIdx.y * 128;
    const int lane = tid & 31, warp = tid >> 5;
    const int wm = warp & 1, wn = warp >> 1;
    const int g  = lane >> 2, tg = lane & 3;

    const float* aptr[4];
    const float* bptr[4];
    int soff[4];
#pragma unroll
    for (int i = 0; i < 4; ++i) {
        int idx = tid + i * 256;
        int row = idx >> 3, cv = idx & 7;
        int arow = g_tok[m0 + row];
        aptr[i] = A + (size_t)arow * HID + cv * 4;
        bptr[i] = Bm + (size_t)(n0 + row) * HID + cv * 4;
        soff[i] = row * 36 + cv * 4;
    }

    float c[4][4][4];
#pragma unroll
    for (int a = 0; a < 4; ++a)
#pragma unroll
        for (int b = 0; b < 4; ++b)
#pragma unroll
            for (int k = 0; k < 4; ++k) c[a][b][k] = 0.f;

    for (int kt = 0; kt < 16; ++kt) {
        float4 va[4], vb[4];
#pragma unroll
        for (int i = 0; i < 4; ++i) {
            va[i] = *(const float4*)(aptr[i] + kt * 32);
            vb[i] = *(const float4*)(bptr[i] + kt * 32);
        }
        __syncthreads();
#pragma unroll
        for (int i = 0; i < 4; ++i) {
            As[soff[i] + 0] = f2tf(va[i].x); As[soff[i] + 1] = f2tf(va[i].y);
            As[soff[i] + 2] = f2tf(va[i].z); As[soff[i] + 3] = f2tf(va[i].w);
            Bs[soff[i] + 0] = f2tf(vb[i].x); Bs[soff[i] + 1] = f2tf(vb[i].y);
            Bs[soff[i] + 2] = f2tf(vb[i].z); Bs[soff[i] + 3] = f2tf(vb[i].w);
        }
        __syncthreads();

#pragma unroll
        for (int kk = 0; kk < 4; ++kk) {
            const int kb = kk * 8;
            unsigned afr[4][4], bfr[4][2];
#pragma unroll
            for (int mf = 0; mf < 4; ++mf) {
                int r0 = (wm * 64 + mf * 16 + g) * 36 + kb + tg;
                afr[mf][0] = As[r0];
                afr[mf][1] = As[r0 + 8 * 36];
                afr[mf][2] = As[r0 + 4];
                afr[mf][3] = As[r0 + 8 * 36 + 4];
            }
#pragma unroll
            for (int nf = 0; nf < 4; ++nf) {
                int r0 = (wn * 32 + nf * 8 + g) * 36 + kb + tg;
                bfr[nf][0] = Bs[r0];
                bfr[nf][1] = Bs[r0 + 4];
            }
#pragma unroll
            for (int mf = 0; mf < 4; ++mf)
#pragma unroll
                for (int nf = 0; nf < 4; ++nf)
                    mma8(c[mf][nf], afr[mf], bfr[nf][0], bfr[nf][1]);
        }
    }

#pragma unroll
    for (int mf = 0; mf < 4; ++mf) {
#pragma unroll
        for (int nf = 0; nf < 4; ++nf) {
            int row = m0 + wm * 64 + mf * 16 + g;
            int col = n0 + wn * 32 + nf * 8 + 2 * tg;
            float b0v = bias[col], b1v = bias[col + 1];
            float2 v0 = make_float2(c[mf][nf][0] + b0v, c[mf][nf][1] + b1v);
            float2 v1 = make_float2(c[mf][nf][2] + b0v, c[mf][nf][3] + b1v);
            *(float2*)&g_xg[(size_t)row * NGATE + col]       = v0;
            *(float2*)&g_xg[(size_t)(row + 8) * NGATE + col] = v1;
        }
    }
}

// ---------------- logits GEMM: fp16 m16n8k16, small-stage cp.async -------
// (unchanged from R13 except both kernels now force the SAME smem carveout
// config so their CTAs can co-locate on one SM)
#define GKH   16            /* halves per chunk */
#define NCHH  32            /* 512 / 16 */
#define RSB   32            /* bytes per row in smem */
#define AWB   (128 * RSB)   /* 4096 B per A stage */
#define STWB  (2 * AWB)     /* 8192 B per stage */
#define SMEMH (3 * STWB)    /* 24576 B */

__global__ void __launch_bounds__(256, 2)
gemm3(const float* __restrict__ bias, float* __restrict__ out) {
    // ---- PDL gate: wait until the scan has produced this tile's rows ----
    {
        const unsigned need = (unsigned)(blockIdx.y * 4 + 4);
        if (threadIdx.x < 32) {
            for (;;) {
                unsigned ok = 1;
#pragma unroll
                for (int i = 0; i < 4; ++i) {
                    unsigned v;
                    asm volatile("ld.acquire.gpu.global.u32 %0, [%1];"
                                 : "=r"(v)
                                 : "l"(&g_arr[(threadIdx.x * 4 + i) * 32])
                                 : "memory");
                    ok &= (v >= need) ? 1u : 0u;
                }
                if (__all_sync(0xffffffffu, ok)) break;
                __nanosleep(256);
            }
        }
        __syncthreads();
    }

    extern __shared__ char smemc[];
    const uint32_t sb = s2u(smemc);
    const int tid  = threadIdx.x;
    const int wid  = tid >> 5, lane = tid & 31;
    const int wm = wid & 1, wn = wid >> 1;         // 2 x 4 warps
    const int g  = lane >> 2, tg = lane & 3;
    const int n0 = blockIdx.x * 128, m0 = blockIdx.y * 128;

    // one 16B cp.async per thread per operand per chunk (256 slots each)
    const int r_ld = tid >> 1, hf_ld = tid & 1;
    const __half* asrc = g_hs_h  + (size_t)(m0 + r_ld) * HID + hf_ld * 8;
    const __half* bsrc = g_wout_h + (size_t)(n0 + r_ld) * HID + hf_ld * 8;
    const uint32_t adst = (uint32_t)(r_ld * RSB + hf_ld * 16);
    const uint32_t bdst = (uint32_t)(AWB + r_ld * RSB + hf_ld * 16);

    float c[4][4][4];
#pragma unroll
    for (int mf = 0; mf < 4; ++mf)
#pragma unroll
        for (int nf = 0; nf < 4; ++nf)
#pragma unroll
            for (int k = 0; k < 4; ++k) c[mf][nf][k] = 0.f;

#pragma unroll
    for (int pc = 0; pc < 2; ++pc) {      // prologue: chunks 0,1
        uint32_t sbase = sb + (uint32_t)(pc * STWB);
        int kb = pc * GKH;
        asm volatile("cp.async.cg.shared.global [%0], [%1], 16;"
                     :: "r"(sbase + adst), "l"(asrc + kb) : "memory");
        asm volatile("cp.async.cg.shared.global [%0], [%1], 16;"
                     :: "r"(sbase + bdst), "l"(bsrc + kb) : "memory");
        asm volatile("cp.async.commit_group;" ::: "memory");
    }

#pragma unroll 1
    for (int ch = 0; ch < NCHH; ++ch) {
        asm volatile("cp.async.wait_group 1;" ::: "memory");  // chunk ch done
        __syncthreads();   // all warps done reading stage (ch+2)%3 (iter ch-1)

        {   // issue chunk ch+2 into stage (ch+2)%3
            int nc = ch + 2;
            if (nc < NCHH) {
                uint32_t sbase = sb + (uint32_t)((nc % 3) * STWB);
                int kb = nc * GKH;
                asm volatile("cp.async.cg.shared.global [%0], [%1], 16;"
                             :: "r"(sbase + adst), "l"(asrc + kb) : "memory");
                asm volatile("cp.async.cg.shared.global [%0], [%1], 16;"
                             :: "r"(sbase + bdst), "l"(bsrc + kb) : "memory");
            }
            asm volatile("cp.async.commit_group;" ::: "memory");
        }

        const uint32_t sbase = sb + (uint32_t)((ch % 3) * STWB);
        uint32_t a[4][4];
#pragma unroll
        for (int mf = 0; mf < 4; ++mf) {
            int r0 = wm * 64 + mf * 16 + g;
            uint32_t ad0 = sbase + (uint32_t)(r0 * RSB + tg * 8);
            uint32_t ad1 = sbase + (uint32_t)((r0 + 8) * RSB + tg * 8);
            asm volatile("ld.shared.v2.b32 {%0,%1}, [%2];"
                         : "=r"(a[mf][0]), "=r"(a[mf][2]) : "r"(ad0));
            asm volatile("ld.shared.v2.b32 {%0,%1}, [%2];"
                         : "=r"(a[mf][1]), "=r"(a[mf][3]) : "r"(ad1));
        }
#pragma unroll
        for (int nf = 0; nf < 4; ++nf) {
            int rn = wn * 32 + nf * 8 + g;
            uint32_t bd = sbase + (uint32_t)(AWB + rn * RSB + tg * 8);
            uint32_t b0, b1;
            asm volatile("ld.shared.v2.b32 {%0,%1}, [%2];"
                         : "=r"(b0), "=r"(b1) : "r"(bd));
#pragma unroll
            for (int mf = 0; mf < 4; ++mf)
                mma16h(c[mf][nf], a[mf][0], a[mf][1], a[mf][2], a[mf][3],
                       b0, b1);
        }
    }

    // epilogue: rows -> (s,b) remap, add bias
#pragma unroll
    for (int mf = 0; mf < 4; ++mf) {
        int row = m0 + wm * 64 + mf * 16 + g;
        int s0 = row >> 5, b0i = row & 31;
        int r1 = row + 8;
        int s1 = r1 >> 5, b1i = r1 & 31;
        float* o0 = out + ((size_t)b0i * SEQ + s0) * VOC;
        float* o1 = out + ((size_t)b1i * SEQ + s1) * VOC;
#pragma unroll
        for (int nf = 0; nf < 4; ++nf) {
            int col = n0 + wn * 32 + nf * 8 + 2 * tg;
            float bv0 = bias[col], bv1 = bias[col + 1];
            *(float2*)(o0 + col) = make_float2(c[mf][nf][0] + bv0,
                                               c[mf][nf][1] + bv1);
            *(float2*)(o1 + col) = make_float2(c[mf][nf][2] + bv0,
                                               c[mf][nf][3] + bv1);
        }
    }
}

// ---------------- persistent GRU scan: 32 j-groups x 4 batch-groups ------
// (unchanged from R11-R13: ~568us, bit-identical outputs)
#define RS_H   0
#define RS_W   4096
#define RS_BI  (RS_W + 48 * HID)
#define RS_XG  (RS_BI + 48)
#define RS_TOT ((RS_XG + 384) * 4)     /* 116416 B */

__global__ void __launch_bounds__(256, 2)
recur_kernel(const float* __restrict__ W_hh, const float* __restrict__ b_hh) {
    // allow the dependent logits GEMM to start launching now
    asm volatile("griddepcontrol.launch_dependents;" ::: "memory");

    extern __shared__ float sm[];
    float* h_sm    = sm + RS_H;
    float* w_sm    = sm + RS_W;
    float* bias_sm = sm + RS_BI;
    float* xg_sm   = sm + RS_XG;
    const uint32_t sb = s2u(sm);

    const int tid = threadIdx.x;
    const int bg  = blockIdx.x & 3;
    const int jg  = blockIdx.x >> 2;
    const int j0  = jg * 16;
    const int bbase = bg * 8;

    // load W slice: 48 rows (16 local j x 3 gates) x 512
    for (int i = tid; i < 48 * HID; i += 256) {
        int r = i >> 9, k = i & 511;
        int lj = r / 3, gg = r % 3;
        w_sm[i] = W_hh[(size_t)(gg * HID + j0 + lj) * HID + k];
    }
    if (tid < 48) {
        int lj = tid / 3, gg = tid % 3;
        bias_sm[tid] = b_hh[gg * HID + j0 + lj];
    }

    const int ks = tid & 15;          // 16-way k split
    const int grp = tid >> 4;         // 16 (bq, jl) groups
    const int bq = grp & 1;           // 2 batch quads (4 b each)
    const int jl = grp >> 1;          // 8 j-pairs: lj = jl*2 + jj
    const float* wp[6];               // [jj*3 + gate]
#pragma unroll
    for (int jj = 0; jj < 2; ++jj)
#pragma unroll
        for (int gg = 0; gg < 3; ++gg)
            wp[jj * 3 + gg] = w_sm + ((jl * 2 + jj) * 3 + gg) * HID;

    // xg staging (tid < 96): 8 b x 3 gates x 4 quarters of 4 j
    const int xbl = tid / 12, xrem = tid - xbl * 12;
    const int xgt = xrem >> 2, xq = xrem & 3;
    const uint32_t xg_dst =
        sb + (uint32_t)((RS_XG + xbl * 48 + xgt * 16 + xq * 4) * 4);
    const float* xg_srcb =
        g_xg + (size_t)(bbase + xbl) * NGATE + xgt * HID + j0 + xq * 4;

    __syncthreads();

    for (int s = 0; s < SEQ; ++s) {
        // stage xg[s] slice (independent of h)
        if (tid < 96) {
            const float* src = xg_srcb + (size_t)s * BSZ * NGATE;
            asm volatile("cp.async.cg.shared.global [%0], [%1], 16;"
                         :: "r"(xg_dst), "l"(src) : "memory");
        }
        // broadcast own batch column's h (8 x 512 = 16KB) into smem
        {
            const float* src = g_h[s & 1] + bbase * HID;
#pragma unroll
            for (int t = 0; t < 4; ++t) {
                int idx = tid + t * 256;
                asm volatile("cp.async.cg.shared.global [%0], [%1], 16;"
                             :: "r"(sb + (uint32_t)((RS_H + idx * 4) * 4)),
                                "l"(src + idx * 4) : "memory");
            }
        }
        asm volatile("cp.async.commit_group;" ::: "memory");
        asm volatile("cp.async.wait_group 0;" ::: "memory");
        __syncthreads();

        unsigned long long acc[6][4];   // [jj*3+gate][bi]
#pragma unroll
        for (int q = 0; q < 6; ++q)
#pragma unroll
            for (int bi = 0; bi < 4; ++bi) acc[q][bi] = 0ull;

#pragma unroll
        for (int i = 0; i < 8; ++i) {
            int k = ks * 4 + i * 64;
            ulonglong2 w2[6];
#pragma unroll
            for (int q = 0; q < 6; ++q)
                w2[q] = *(const ulonglong2*)(wp[q] + k);
#pragma unroll
            for (int bi = 0; bi < 4; ++bi) {
                int bl = bq * 4 + bi;
                ulonglong2 h2 = *(const ulonglong2*)(h_sm + bl * HID + k);
#pragma unroll
                for (int q = 0; q < 6; ++q) {
                    fma2(acc[q][bi], h2.x, w2[q].x);
                    fma2(acc[q][bi], h2.y, w2[q].y);
                }
            }
        }
        float a[6][4];
#pragma unroll
        for (int q = 0; q < 6; ++q)
#pragma unroll
            for (int bi = 0; bi < 4; ++bi) a[q][bi] = pairsum(acc[q][bi]);
        // reduce across the 16 k-split lanes
#pragma unroll
        for (int off = 8; off > 0; off >>= 1) {
#pragma unroll
            for (int q = 0; q < 6; ++q)
#pragma unroll
                for (int bi = 0; bi < 4; ++bi)
                    a[q][bi] += __shfl_xor_sync(0xffffffffu, a[q][bi], off);
        }
        if (ks == 0) {
#pragma unroll
            for (int jj = 0; jj < 2; ++jj) {
                int lj = jl * 2 + jj;
                int j  = j0 + lj;
                float br = bias_sm[lj * 3 + 0];
                float bz = bias_sm[lj * 3 + 1];
                float bn = bias_sm[lj * 3 + 2];
#pragma unroll
                for (int bi = 0; bi < 4; ++bi) {
                    int bl = bq * 4 + bi;
                    int b  = bbase + bl;
                    float rr = fsigm(xg_sm[bl * 48 + 0  + lj] + a[jj * 3 + 0][bi] + br);
                    float zz = fsigm(xg_sm[bl * 48 + 16 + lj] + a[jj * 3 + 1][bi] + bz);
                    float nn = ftanh(xg_sm[bl * 48 + 32 + lj] +
                                     rr * (a[jj * 3 + 2][bi] + bn));
                    float hold = h_sm[bl * HID + j];
                    float hnew = (1.f - zz) * nn + zz * hold;
                    g_h[(s + 1) & 1][b * HID + j] = hnew;
                    g_hs_h[(size_t)(s * BSZ + b) * HID + j] =
                        __float2half_rn(hnew);
                }
            }
        }
        if (s == SEQ - 1) break;

        // ---- column barrier: store-arrive + poll own 32 CTAs ----
        __syncthreads();
        const unsigned sv = (unsigned)(s + 1);
        if (tid == 0) {
            asm volatile("st.release.gpu.global.u32 [%0], %1;"
                         :: "l"(&g_arr[blockIdx.x * 32]), "r"(sv) : "memory");
        }
        if (tid < 32) {
            int cc = tid * 4 + bg;     // same-column CTA ids
            for (;;) {
                unsigned v;
                asm volatile("ld.acquire.gpu.global.u32 %0, [%1];"
                             : "=r"(v) : "l"(&g_arr[cc * 32]) : "memory");
                if (__all_sync(0xffffffffu, (v >= sv) ? 1u : 0u)) break;
            }
        }
        __syncthreads();
    }

    // final arrival: publish step 128 (releases last M-tiles to gemm3)
    __syncthreads();
    if (tid == 0) {
        asm volatile("st.release.gpu.global.u32 [%0], %1;"
                     :: "l"(&g_arr[blockIdx.x * 32]), "r"((unsigned)SEQ)
                     : "memory");
    }
}

// ---------------- launch ----------------
extern "C" void kernel_launch(void* const* d_in, const int* in_sizes, int n_in,
                              void* d_out, int out_size) {
    const float* hidden    = (const float*)d_in[0];
    const void*  targets   = (const void*)d_in[1];
    const float* embedding = (const float*)d_in[2];
    const float* W_ih      = (const float*)d_in[3];
    const float* W_hh      = (const float*)d_in[4];
    const float* b_ih      = (const float*)d_in[5];
    const float* b_hh      = (const float*)d_in[6];
    const float* W_out     = (const float*)d_in[7];
    const float* b_out     = (const float*)d_in[8];
    const int*   init_tok  = (const int*)d_in[9];
    float*       out       = (float*)d_out;

    cudaFuncSetAttribute(recur_kernel,
                         cudaFuncAttributeMaxDynamicSharedMemorySize, RS_TOT);
    cudaFuncSetAttribute(gemm3,
                         cudaFuncAttributeMaxDynamicSharedMemorySize, SMEMH);
    // force BOTH kernels into the SAME (max) smem carveout config so their
    // CTAs can co-locate on an SM (configs must match for co-residency;
    // see R7-R13 bucket table)
    cudaFuncSetAttribute(recur_kernel,
                         cudaFuncAttributePreferredSharedMemoryCarveout, 100);
    cudaFuncSetAttribute(gemm3,
                         cudaFuncAttributePreferredSharedMemoryCarveout, 100);

    init_kernel<<<16, 256>>>(targets, init_tok, hidden);

    // x_gates: [4096 x 1536 x 512], A gathered from embedding
    gemm_xg<<<dim3(NGATE / 128, NTOK / 128), 256>>>(embedding, W_ih, b_ih);

    // pre-round W_out to fp16 (RN)
    conv_w<<<256, 256>>>(W_out);

    // sequential GRU scan (persistent, 128 co-resident CTAs)
    recur_kernel<<<128, 256, RS_TOT>>>(W_hh, b_hh);

    // logits GEMM (fp16, 24.6KB smem), PDL-overlapped with the scan
    {
        cudaLaunchConfig_t cfg = {};
        cfg.gridDim  = dim3(VOC / 128, NTOK / 128);
        cfg.blockDim = dim3(256);
        cfg.dynamicSmemBytes = SMEMH;
        cudaLaunchAttribute attr[1];
        attr[0].id = cudaLaunchAttributeProgrammaticStreamSerialization;
        attr[0].val.programmaticStreamSerializationAllowed = 1;
        cfg.attrs = attr;
        cfg.numAttrs = 1;
        cudaLaunchKernelEx(&cfg, gemm3, (const float*)b_out, out);
    }
}

// round 15
// speedup vs baseline: 1.2283x; 1.0457x over previous
#include <cuda_runtime.h>
#include <cuda_fp16.h>
#include <cstdint>
#include <cmath>

#define BSZ   32
#define SEQ   128
#define HID   512
#define NGATE 1536
#define VOC   32000
#define NTOK  4096   /* BSZ*SEQ */

// ---------------- device scratch (no allocations allowed) ----------------
__device__ int      g_tok[NTOK];
__device__ float    g_xg[(size_t)NTOK * NGATE];    // [S][B][3H], b_ih folded in
__device__ __half   g_hs_h[(size_t)NTOK * HID];    // fp16 hidden states
__device__ __half   g_wout_h[(size_t)VOC * HID];   // fp16 W_out
__device__ float    g_h[2][BSZ * HID];             // ping-pong hidden state
__device__ unsigned g_arr[128 * 32];               // per-CTA arrival slots (128B apart)

__device__ __forceinline__ unsigned f2tf(float x) {
    unsigned r;
    asm("cvt.rna.tf32.f32 %0, %1;" : "=r"(r) : "f"(x));
    return r;
}
__device__ __forceinline__ uint32_t s2u(const void* p) {
    uint32_t a;
    asm("{ .reg .u64 t; cvta.to.shared.u64 t, %1; cvt.u32.u64 %0, t; }"
        : "=r"(a) : "l"(p));
    return a;
}
// packed fp32x2 FMA: d = a*b + d  (two exact fp32 FMAs in one instruction)
__device__ __forceinline__ void fma2(unsigned long long& d,
                                     unsigned long long a,
                                     unsigned long long b) {
    asm("fma.rn.f32x2 %0, %1, %2, %0;" : "+l"(d) : "l"(a), "l"(b));
}
__device__ __forceinline__ float pairsum(unsigned long long v) {
    unsigned lo, hi;
    asm("mov.b64 {%0, %1}, %2;" : "=r"(lo), "=r"(hi) : "l"(v));
    return __uint_as_float(lo) + __uint_as_float(hi);
}

// targets may be int32 (JAX x64 disabled) or int64. Detect: int64 tokens
// always have zero high words -> first 8 int64 views all in [0, VOC).
__device__ __forceinline__ bool tok_is64(const void* p) {
    const long long* q = (const long long*)p;
    bool ok = true;
#pragma unroll
    for (int i = 0; i < 8; ++i) {
        long long v = q[i];
        ok = ok && (v >= 0) && (v < VOC);
    }
    return ok;
}
__device__ __forceinline__ int tok_at(const void* p, int idx, bool is64) {
    return is64 ? (int)((const long long*)p)[idx] : ((const int*)p)[idx];
}

__device__ __forceinline__ float fsigm(float x) {
    return __fdividef(1.f, 1.f + __expf(-x));
}
__device__ __forceinline__ float ftanh(float x) {
    float ax = fabsf(x);
    float e  = __expf(-2.f * ax);
    float t  = __fdividef(1.f - e, 1.f + e);
    return copysignf(t, x);
}

__device__ __forceinline__ void mma8(float* c, const uint32_t* a,
                                     uint32_t b0, uint32_t b1) {
    asm volatile(
        "mma.sync.aligned.m16n8k8.row.col.f32.tf32.tf32.f32 "
        "{%0,%1,%2,%3}, {%4,%5,%6,%7}, {%8,%9}, {%0,%1,%2,%3};"
        : "+f"(c[0]), "+f"(c[1]), "+f"(c[2]), "+f"(c[3])
        : "r"(a[0]), "r"(a[1]), "r"(a[2]), "r"(a[3]), "r"(b0), "r"(b1));
}
__device__ __forceinline__ void mma16h(float* c, uint32_t a0, uint32_t a1,
                                       uint32_t a2, uint32_t a3,
                                       uint32_t b0, uint32_t b1) {
    asm volatile(
        "mma.sync.aligned.m16n8k16.row.col.f32.f16.f16.f32 "
        "{%0,%1,%2,%3}, {%4,%5,%6,%7}, {%8,%9}, {%0,%1,%2,%3};"
        : "+f"(c[0]), "+f"(c[1]), "+f"(c[2]), "+f"(c[3])
        : "r"(a0), "r"(a1), "r"(a2), "r"(a3), "r"(b0), "r"(b1));
}

// ---------------- init: token indices, h0, barrier reset -----------------
__global__ void init_kernel(const void* __restrict__ targets,
                            const int* __restrict__ init_tok,
                            const float* __restrict__ hidden) {
    const bool is64 = tok_is64(targets);
    int t = blockIdx.x * blockDim.x + threadIdx.x;
    int nt = gridDim.x * blockDim.x;
    for (int i = t; i < 128 * 32; i += nt) g_arr[i] = 0u;
    if (t < NTOK) {
        int s = t >> 5, b = t & 31;
        g_tok[t] = (s == 0) ? init_tok[0]
                            : tok_at(targets, b * SEQ + (s - 1), is64);
    }
    for (int i = t; i < BSZ * HID; i += nt)
        g_h[0][i] = hidden[i];
}

// ---------------- pre-convert W_out to fp16 (RN) -------------------------
__global__ void conv_w(const float* __restrict__ W) {
    int t = blockIdx.x * blockDim.x + threadIdx.x;
    int nt = gridDim.x * blockDim.x;
    const int n4 = (VOC * HID) / 4;
    for (int i = t; i < n4; i += nt) {
        float4 v = ((const float4*)W)[i];
        __half2 h01 = __floats2half2_rn(v.x, v.y);
        __half2 h23 = __floats2half2_rn(v.z, v.w);
        *(__half2*)(g_wout_h + (size_t)i * 4)     = h01;
        *(__half2*)(g_wout_h + (size_t)i * 4 + 2) = h23;
    }
}

// ---------------- x_gates GEMM (embedding gather, tf32 mma.sync) ---------
__global__ void __launch_bounds__(256, 2)
gemm_xg(const float* __restrict__ A, const float* __restrict__ Bm,
        const float* __restrict__ bias) {
    __shared__ unsigned As[128 * 36];
    __shared__ unsigned Bs[128 * 36];

    const int tid  = threadIdx.x;
    const int n0   = blockIdx.x * 128;
    const int m0   = blockIdx.y * 128;
    const int lane = tid & 31, warp = tid >> 5;
    const int wm = warp & 1, wn = warp >> 1;
    const int g  = lane >> 2, tg = lane & 3;

    const float* aptr[4];
    const float* bptr[4];
    int soff[4];
#pragma unroll
    for (int i = 0; i < 4; ++i) {
        int idx = tid + i * 256;
        int row = idx >> 3, cv = idx & 7;
        int arow = g_tok[m0 + row];
        aptr[i] = A + (size_t)arow * HID + cv * 4;
        bptr[i] = Bm + (size_t)(n0 + row) * HID + cv * 4;
        soff[i] = row * 36 + cv * 4;
    }

    float c[4][4][4];
#pragma unroll
    for (int a = 0; a < 4; ++a)
#pragma unroll
        for (int b = 0; b < 4; ++b)
#pragma unroll
            for (int k = 0; k < 4; ++k) c[a][b][k] = 0.f;

    for (int kt = 0; kt < 16; ++kt) {
        float4 va[4], vb[4];
#pragma unroll
        for (int i = 0; i < 4; ++i) {
            va[i] = *(const float4*)(aptr[i] + kt * 32);
            vb[i] = *(const float4*)(bptr[i] + kt * 32);
        }
        __syncthreads();
#pragma unroll
        for (int i = 0; i < 4; ++i) {
            As[soff[i] + 0] = f2tf(va[i].x); As[soff[i] + 1] = f2tf(va[i].y);
            As[soff[i] + 2] = f2tf(va[i].z); As[soff[i] + 3] = f2tf(va[i].w);
            Bs[soff[i] + 0] = f2tf(vb[i].x); Bs[soff[i] + 1] = f2tf(vb[i].y);
            Bs[soff[i] + 2] = f2tf(vb[i].z); Bs[soff[i] + 3] = f2tf(vb[i].w);
        }
        __syncthreads();

#pragma unroll
        for (int kk = 0; kk < 4; ++kk) {
            const int kb = kk * 8;
            unsigned afr[4][4], bfr[4][2];
#pragma unroll
            for (int mf = 0; mf < 4; ++mf) {
                int r0 = (wm * 64 + mf * 16 + g) * 36 + kb + tg;
                afr[mf][0] = As[r0];
                afr[mf][1] = As[r0 + 8 * 36];
                afr[mf][2] = As[r0 + 4];
                afr[mf][3] = As[r0 + 8 * 36 + 4];
            }
#pragma unroll
            for (int nf = 0; nf < 4; ++nf) {
                int r0 = (wn * 32 + nf * 8 + g) * 36 + kb + tg;
                bfr[nf][0] = Bs[r0];
                bfr[nf][1] = Bs[r0 + 4];
            }
#pragma unroll
            for (int mf = 0; mf < 4; ++mf)
#pragma unroll
                for (int nf = 0; nf < 4; ++nf)
                    mma8(c[mf][nf], afr[mf], bfr[nf][0], bfr[nf][1]);
        }
    }

#pragma unroll
    for (int mf = 0; mf < 4; ++mf) {
#pragma unroll
        for (int nf = 0; nf < 4; ++nf) {
            int row = m0 + wm * 64 + mf * 16 + g;
            int col = n0 + wn * 32 + nf * 8 + 2 * tg;
            float b0v = bias[col], b1v = bias[col + 1];
            float2 v0 = make_float2(c[mf][nf][0] + b0v, c[mf][nf][1] + b1v);
            float2 v1 = make_float2(c[mf][nf][2] + b0v, c[mf][nf][3] + b1v);
            *(float2*)&g_xg[(size_t)row * NGATE + col]       = v0;
            *(float2*)&g_xg[(size_t)(row + 8) * NGATE + col] = v1;
        }
    }
}

// ---------------- logits GEMM: fp16 m16n8k16, K=32 chunks, 4 stages ------
// 96B rows (conflict-free LDS.64 fragment pairs), 16 chunks -> half the
// syncs of the 16-half variant; 4-stage ring (98.3KB) rides over scan
// L2-traffic bursts during overlap. recur(116.4) + gemm3(98.3) = 214.7KB
// <= 228KB and regs 32K+32K = 64K with both at carveout 100 -> co-resident.
#define GKH   32            /* halves per chunk */
#define NCHH  16            /* 512 / 32 */
#define RSB   96            /* bytes per row in smem */
#define AWB   (128 * RSB)   /* 12288 B per A stage */
#define STWB  (2 * AWB)     /* 24576 B per stage */
#define NSTG  4
#define SMEMH (NSTG * STWB) /* 98304 B */

__global__ void __launch_bounds__(256, 2)
gemm3(const float* __restrict__ bias, float* __restrict__ out) {
    // ---- PDL gate: wait until the scan has produced this tile's rows ----
    {
        const unsigned need = (unsigned)(blockIdx.y * 4 + 4);
        if (threadIdx.x < 32) {
            for (;;) {
                unsigned ok = 1;
#pragma unroll
                for (int i = 0; i < 4; ++i) {
                    unsigned v;
                    asm volatile("ld.acquire.gpu.global.u32 %0, [%1];"
                                 : "=r"(v)
                                 : "l"(&g_arr[(threadIdx.x * 4 + i) * 32])
                                 : "memory");
                    ok &= (v >= need) ? 1u : 0u;
                }
                if (__all_sync(0xffffffffu, ok)) break;
                __nanosleep(256);
            }
        }
        __syncthreads();
    }

    extern __shared__ char smemc[];
    const uint32_t sb = s2u(smemc);
    const int tid  = threadIdx.x;
    const int wid  = tid >> 5, lane = tid & 31;
    const int wm = wid & 1, wn = wid >> 1;         // 2 x 4 warps
    const int g  = lane >> 2, tg = lane & 3;
    const int n0 = blockIdx.x * 128, m0 = blockIdx.y * 128;

    const __half* asrc[2]; uint32_t adst[2];
    const __half* bsrc[2]; uint32_t bdst[2];
#pragma unroll
    for (int i = 0; i < 2; ++i) {
        int idx = tid + i * 256, r = idx >> 2, c4 = idx & 3;
        asrc[i] = g_hs_h + (size_t)(m0 + r) * HID + c4 * 8;
        adst[i] = (uint32_t)(r * RSB + c4 * 16);
        bsrc[i] = g_wout_h + (size_t)(n0 + r) * HID + c4 * 8;
        bdst[i] = (uint32_t)(AWB + r * RSB + c4 * 16);
    }

    float c[4][4][4];
#pragma unroll
    for (int mf = 0; mf < 4; ++mf)
#pragma unroll
        for (int nf = 0; nf < 4; ++nf)
#pragma unroll
            for (int k = 0; k < 4; ++k) c[mf][nf][k] = 0.f;

#pragma unroll
    for (int pc = 0; pc < 3; ++pc) {      // prologue: chunks 0..2
        uint32_t sbase = sb + (uint32_t)(pc * STWB);
        int kb = pc * GKH;
#pragma unroll
        for (int i = 0; i < 2; ++i) {
            asm volatile("cp.async.cg.shared.global [%0], [%1], 16;"
                         :: "r"(sbase + adst[i]), "l"(asrc[i] + kb) : "memory");
            asm volatile("cp.async.cg.shared.global [%0], [%1], 16;"
                         :: "r"(sbase + bdst[i]), "l"(bsrc[i] + kb) : "memory");
        }
        asm volatile("cp.async.commit_group;" ::: "memory");
    }

#pragma unroll 1
    for (int ch = 0; ch < NCHH; ++ch) {
        asm volatile("cp.async.wait_group 2;" ::: "memory");  // chunk ch done
        __syncthreads();   // also: stage (ch+3)%4 fully read at iter ch-1

        {   // issue chunk ch+3 into stage (ch+3)%4
            int nc = ch + 3;
            if (nc < NCHH) {
                uint32_t sbase = sb + (uint32_t)((nc % NSTG) * STWB);
                int kb = nc * GKH;
#pragma unroll
                for (int i = 0; i < 2; ++i) {
                    asm volatile("cp.async.cg.shared.global [%0], [%1], 16;"
                                 :: "r"(sbase + adst[i]), "l"(asrc[i] + kb)
                                 : "memory");
                    asm volatile("cp.async.cg.shared.global [%0], [%1], 16;"
                                 :: "r"(sbase + bdst[i]), "l"(bsrc[i] + kb)
                                 : "memory");
                }
            }
            asm volatile("cp.async.commit_group;" ::: "memory");
        }

        const uint32_t sbase = sb + (uint32_t)((ch % NSTG) * STWB);
#pragma unroll
        for (int kk = 0; kk < 2; ++kk) {       // two k16 slices per chunk
            uint32_t a[4][4];
#pragma unroll
            for (int mf = 0; mf < 4; ++mf) {
                int r0 = wm * 64 + mf * 16 + g;
                uint32_t ad0 = sbase + (uint32_t)(r0 * RSB + kk * 32 + tg * 8);
                uint32_t ad1 = sbase +
                    (uint32_t)((r0 + 8) * RSB + kk * 32 + tg * 8);
                asm volatile("ld.shared.v2.b32 {%0,%1}, [%2];"
                             : "=r"(a[mf][0]), "=r"(a[mf][2]) : "r"(ad0));
                asm volatile("ld.shared.v2.b32 {%0,%1}, [%2];"
                             : "=r"(a[mf][1]), "=r"(a[mf][3]) : "r"(ad1));
            }
#pragma unroll
            for (int nf = 0; nf < 4; ++nf) {
                int rn = wn * 32 + nf * 8 + g;
                uint32_t bd = sbase +
                    (uint32_t)(AWB + rn * RSB + kk * 32 + tg * 8);
                uint32_t b0, b1;
                asm volatile("ld.shared.v2.b32 {%0,%1}, [%2];"
                             : "=r"(b0), "=r"(b1) : "r"(bd));
#pragma unroll
                for (int mf = 0; mf < 4; ++mf)
                    mma16h(c[mf][nf], a[mf][0], a[mf][1], a[mf][2], a[mf][3],
                           b0, b1);
            }
        }
    }

    // epilogue: rows -> (s,b) remap, add bias
#pragma unroll
    for (int mf = 0; mf < 4; ++mf) {
        int row = m0 + wm * 64 + mf * 16 + g;
        int s0 = row >> 5, b0i = row & 31;
        int r1 = row + 8;
        int s1 = r1 >> 5, b1i = r1 & 31;
        float* o0 = out + ((size_t)b0i * SEQ + s0) * VOC;
        float* o1 = out + ((size_t)b1i * SEQ + s1) * VOC;
#pragma unroll
        for (int nf = 0; nf < 4; ++nf) {
            int col = n0 + wn * 32 + nf * 8 + 2 * tg;
            float bv0 = bias[col], bv1 = bias[col + 1];
            *(float2*)(o0 + col) = make_float2(c[mf][nf][0] + bv0,
                                               c[mf][nf][1] + bv1);
            *(float2*)(o1 + col) = make_float2(c[mf][nf][2] + bv0,
                                               c[mf][nf][3] + bv1);
        }
    }
}

// ---------------- persistent GRU scan: 32 j-groups x 4 batch-groups ------
// (unchanged from R11-R14: ~570us, bit-identical outputs)
#define RS_H   0
#define RS_W   4096
#define RS_BI  (RS_W + 48 * HID)
#define RS_XG  (RS_BI + 48)
#define RS_TOT ((RS_XG + 384) * 4)     /* 116416 B */

__global__ void __launch_bounds__(256, 2)
recur_kernel(const float* __restrict__ W_hh, const float* __restrict__ b_hh) {
    // allow the dependent logits GEMM to start launching now
    asm volatile("griddepcontrol.launch_dependents;" ::: "memory");

    extern __shared__ float sm[];
    float* h_sm    = sm + RS_H;
    float* w_sm    = sm + RS_W;
    float* bias_sm = sm + RS_BI;
    float* xg_sm   = sm + RS_XG;
    const uint32_t sb = s2u(sm);

    const int tid = threadIdx.x;
    const int bg  = blockIdx.x & 3;
    const int jg  = blockIdx.x >> 2;
    const int j0  = jg * 16;
    const int bbase = bg * 8;

    // load W slice: 48 rows (16 local j x 3 gates) x 512
    for (int i = tid; i < 48 * HID; i += 256) {
        int r = i >> 9, k = i & 511;
        int lj = r / 3, gg = r % 3;
        w_sm[i] = W_hh[(size_t)(gg * HID + j0 + lj) * HID + k];
    }
    if (tid < 48) {
        int lj = tid / 3, gg = tid % 3;
        bias_sm[tid] = b_hh[gg * HID + j0 + lj];
    }

    const int ks = tid & 15;          // 16-way k split
    const int grp = tid >> 4;         // 16 (bq, jl) groups
    const int bq = grp & 1;           // 2 batch quads (4 b each)
    const int jl = grp >> 1;          // 8 j-pairs: lj = jl*2 + jj
    const float* wp[6];               // [jj*3 + gate]
#pragma unroll
    for (int jj = 0; jj < 2; ++jj)
#pragma unroll
        for (int gg = 0; gg < 3; ++gg)
            wp[jj * 3 + gg] = w_sm + ((jl * 2 + jj) * 3 + gg) * HID;

    // xg staging (tid < 96): 8 b x 3 gates x 4 quarters of 4 j
    const int xbl = tid / 12, xrem = tid - xbl * 12;
    const int xgt = xrem >> 2, xq = xrem & 3;
    const uint32_t xg_dst =
        sb + (uint32_t)((RS_XG + xbl * 48 + xgt * 16 + xq * 4) * 4);
    const float* xg_srcb =
        g_xg + (size_t)(bbase + xbl) * NGATE + xgt * HID + j0 + xq * 4;

    __syncthreads();

    for (int s = 0; s < SEQ; ++s) {
        // stage xg[s] slice (independent of h)
        if (tid < 96) {
            const float* src = xg_srcb + (size_t)s * BSZ * NGATE;
            asm volatile("cp.async.cg.shared.global [%0], [%1], 16;"
                         :: "r"(xg_dst), "l"(src) : "memory");
        }
        // broadcast own batch column's h (8 x 512 = 16KB) into smem
        {
            const float* src = g_h[s & 1] + bbase * HID;
#pragma unroll
            for (int t = 0; t < 4; ++t) {
                int idx = tid + t * 256;
                asm volatile("cp.async.cg.shared.global [%0], [%1], 16;"
                             :: "r"(sb + (uint32_t)((RS_H + idx * 4) * 4)),
                                "l"(src + idx * 4) : "memory");
            }
        }
        asm volatile("cp.async.commit_group;" ::: "memory");
        asm volatile("cp.async.wait_group 0;" ::: "memory");
        __syncthreads();

        unsigned long long acc[6][4];   // [jj*3+gate][bi]
#pragma unroll
        for (int q = 0; q < 6; ++q)
#pragma unroll
            for (int bi = 0; bi < 4; ++bi) acc[q][bi] = 0ull;

#pragma unroll
        for (int i = 0; i < 8; ++i) {
            int k = ks * 4 + i * 64;
            ulonglong2 w2[6];
#pragma unroll
            for (int q = 0; q < 6; ++q)
                w2[q] = *(const ulonglong2*)(wp[q] + k);
#pragma unroll
            for (int bi = 0; bi < 4; ++bi) {
                int bl = bq * 4 + bi;
                ulonglong2 h2 = *(const ulonglong2*)(h_sm + bl * HID + k);
#pragma unroll
                for (int q = 0; q < 6; ++q) {
                    fma2(acc[q][bi], h2.x, w2[q].x);
                    fma2(acc[q][bi], h2.y, w2[q].y);
                }
            }
        }
        float a[6][4];
#pragma unroll
        for (int q = 0; q < 6; ++q)
#pragma unroll
            for (int bi = 0; bi < 4; ++bi) a[q][bi] = pairsum(acc[q][bi]);
        // reduce across the 16 k-split lanes
#pragma unroll
        for (int off = 8; off > 0; off >>= 1) {
#pragma unroll
            for (int q = 0; q < 6; ++q)
#pragma unroll
                for (int bi = 0; bi < 4; ++bi)
                    a[q][bi] += __shfl_xor_sync(0xffffffffu, a[q][bi], off);
        }
        if (ks == 0) {
#pragma unroll
            for (int jj = 0; jj < 2; ++jj) {
                int lj = jl * 2 + jj;
                int j  = j0 + lj;
                float br = bias_sm[lj * 3 + 0];
                float bz = bias_sm[lj * 3 + 1];
                float bn = bias_sm[lj * 3 + 2];
#pragma unroll
                for (int bi = 0; bi < 4; ++bi) {
                    int bl = bq * 4 + bi;
                    int b  = bbase + bl;
                    float rr = fsigm(xg_sm[bl * 48 + 0  + lj] + a[jj * 3 + 0][bi] + br);
                    float zz = fsigm(xg_sm[bl * 48 + 16 + lj] + a[jj * 3 + 1][bi] + bz);
                    float nn = ftanh(xg_sm[bl * 48 + 32 + lj] +
                                     rr * (a[jj * 3 + 2][bi] + bn));
                    float hold = h_sm[bl * HID + j];
                    float hnew = (1.f - zz) * nn + zz * hold;
                    g_h[(s + 1) & 1][b * HID + j] = hnew;
                    g_hs_h[(size_t)(s * BSZ + b) * HID + j] =
                        __float2half_rn(hnew);
                }
            }
        }
        if (s == SEQ - 1) break;

        // ---- column barrier: store-arrive + poll own 32 CTAs ----
        __syncthreads();
        const unsigned sv = (unsigned)(s + 1);
        if (tid == 0) {
            asm volatile("st.release.gpu.global.u32 [%0], %1;"
                         :: "l"(&g_arr[blockIdx.x * 32]), "r"(sv) : "memory");
        }
        if (tid < 32) {
            int cc = tid * 4 + bg;     // same-column CTA ids
            for (;;) {
                unsigned v;
                asm volatile("ld.acquire.gpu.global.u32 %0, [%1];"
                             : "=r"(v) : "l"(&g_arr[cc * 32]) : "memory");
                if (__all_sync(0xffffffffu, (v >= sv) ? 1u : 0u)) break;
            }
        }
        __syncthreads();
    }

    // final arrival: publish step 128 (releases last M-tiles to gemm3)
    __syncthreads();
    if (tid == 0) {
        asm volatile("st.release.gpu.global.u32 [%0], %1;"
                     :: "l"(&g_arr[blockIdx.x * 32]), "r"((unsigned)SEQ)
                     : "memory");
    }
}

// ---------------- launch ----------------
extern "C" void kernel_launch(void* const* d_in, const int* in_sizes, int n_in,
                              void* d_out, int out_size) {
    const float* hidden    = (const float*)d_in[0];
    const void*  targets   = (const void*)d_in[1];
    const float* embedding = (const float*)d_in[2];
    const float* W_ih      = (const float*)d_in[3];
    const float* W_hh      = (const float*)d_in[4];
    const float* b_ih      = (const float*)d_in[5];
    const float* b_hh      = (const float*)d_in[6];
    const float* W_out     = (const float*)d_in[7];
    const float* b_out     = (const float*)d_in[8];
    const int*   init_tok  = (const int*)d_in[9];
    float*       out       = (float*)d_out;

    cudaFuncSetAttribute(recur_kernel,
                         cudaFuncAttributeMaxDynamicSharedMemorySize, RS_TOT);
    cudaFuncSetAttribute(gemm3,
                         cudaFuncAttributeMaxDynamicSharedMemorySize, SMEMH);
    // force BOTH kernels into the SAME (max) smem carveout config so their
    // CTAs can co-locate on an SM (configs must match for co-residency)
    cudaFuncSetAttribute(recur_kernel,
                         cudaFuncAttributePreferredSharedMemoryCarveout, 100);
    cudaFuncSetAttribute(gemm3,
                         cudaFuncAttributePreferredSharedMemoryCarveout, 100);

    init_kernel<<<16, 256>>>(targets, init_tok, hidden);

    // x_gates: [4096 x 1536 x 512], A gathered from embedding
    gemm_xg<<<dim3(NGATE / 128, NTOK / 128), 256>>>(embedding, W_ih, b_ih);

    // pre-round W_out to fp16 (RN)
    conv_w<<<256, 256>>>(W_out);

    // sequential GRU scan (persistent, 128 co-resident CTAs)
    recur_kernel<<<128, 256, RS_TOT>>>(W_hh, b_hh);

    // logits GEMM (fp16, 4-stage, 98.3KB smem), PDL-overlapped with scan
    {
        cudaLaunchConfig_t cfg = {};
        cfg.gridDim  = dim3(VOC / 128, NTOK / 128);
        cfg.blockDim = dim3(256);
        cfg.dynamicSmemBytes = SMEMH;
        cudaLaunchAttribute attr[1];
        attr[0].id = cudaLaunchAttributeProgrammaticStreamSerialization;
        attr[0].val.programmaticStreamSerializationAllowed = 1;
        cfg.attrs = attr;
        cfg.numAttrs = 1;
        cudaLaunchKernelEx(&cfg, gemm3, (const float*)b_out, out);
    }
}

// round 16
// speedup vs baseline: 1.2292x; 1.0007x over previous
#include <cuda_runtime.h>
#include <cuda_fp16.h>
#include <cstdint>
#include <cmath>

#define BSZ   32
#define SEQ   128
#define HID   512
#define NGATE 1536
#define VOC   32000
#define NTOK  4096   /* BSZ*SEQ */

// ---------------- device scratch (no allocations allowed) ----------------
__device__ int      g_tok[NTOK];
__device__ float    g_xg[(size_t)NTOK * NGATE];    // [S][B][3H], b_ih folded in
__device__ __half   g_hs_h[(size_t)NTOK * HID];    // fp16 hidden states
__device__ __half   g_wout_h[(size_t)VOC * HID];   // fp16 W_out
__device__ float    g_h[2][BSZ * HID];             // ping-pong hidden state
__device__ unsigned g_arr[128 * 32];               // per-CTA arrival slots (128B apart)

__device__ __forceinline__ unsigned f2tf(float x) {
    unsigned r;
    asm("cvt.rna.tf32.f32 %0, %1;" : "=r"(r) : "f"(x));
    return r;
}
__device__ __forceinline__ uint32_t s2u(const void* p) {
    uint32_t a;
    asm("{ .reg .u64 t; cvta.to.shared.u64 t, %1; cvt.u32.u64 %0, t; }"
        : "=r"(a) : "l"(p));
    return a;
}
// packed fp32x2 FMA: d = a*b + d  (two exact fp32 FMAs in one instruction)
__device__ __forceinline__ void fma2(unsigned long long& d,
                                     unsigned long long a,
                                     unsigned long long b) {
    asm("fma.rn.f32x2 %0, %1, %2, %0;" : "+l"(d) : "l"(a), "l"(b));
}
__device__ __forceinline__ float pairsum(unsigned long long v) {
    unsigned lo, hi;
    asm("mov.b64 {%0, %1}, %2;" : "=r"(lo), "=r"(hi) : "l"(v));
    return __uint_as_float(lo) + __uint_as_float(hi);
}

// targets may be int32 (JAX x64 disabled) or int64. Detect: int64 tokens
// always have zero high words -> first 8 int64 views all in [0, VOC).
__device__ __forceinline__ bool tok_is64(const void* p) {
    const long long* q = (const long long*)p;
    bool ok = true;
#pragma unroll
    for (int i = 0; i < 8; ++i) {
        long long v = q[i];
        ok = ok && (v >= 0) && (v < VOC);
    }
    return ok;
}
__device__ __forceinline__ int tok_at(const void* p, int idx, bool is64) {
    return is64 ? (int)((const long long*)p)[idx] : ((const int*)p)[idx];
}

__device__ __forceinline__ float fsigm(float x) {
    return __fdividef(1.f, 1.f + __expf(-x));
}
__device__ __forceinline__ float ftanh(float x) {
    float ax = fabsf(x);
    float e  = __expf(-2.f * ax);
    float t  = __fdividef(1.f - e, 1.f + e);
    return copysignf(t, x);
}

__device__ __forceinline__ void mma8(float* c, const uint32_t* a,
                                     uint32_t b0, uint32_t b1) {
    asm volatile(
        "mma.sync.aligned.m16n8k8.row.col.f32.tf32.tf32.f32 "
        "{%0,%1,%2,%3}, {%4,%5,%6,%7}, {%8,%9}, {%0,%1,%2,%3};"
        : "+f"(c[0]), "+f"(c[1]), "+f"(c[2]), "+f"(c[3])
        : "r"(a[0]), "r"(a[1]), "r"(a[2]), "r"(a[3]), "r"(b0), "r"(b1));
}
__device__ __forceinline__ void mma16h(float* c, uint32_t a0, uint32_t a1,
                                       uint32_t a2, uint32_t a3,
                                       uint32_t b0, uint32_t b1) {
    asm volatile(
        "mma.sync.aligned.m16n8k16.row.col.f32.f16.f16.f32 "
        "{%0,%1,%2,%3}, {%4,%5,%6,%7}, {%8,%9}, {%0,%1,%2,%3};"
        : "+f"(c[0]), "+f"(c[1]), "+f"(c[2]), "+f"(c[3])
        : "r"(a0), "r"(a1), "r"(a2), "r"(a3), "r"(b0), "r"(b1));
}

// ---------------- init: token indices, h0, barrier reset -----------------
__global__ void init_kernel(const void* __restrict__ targets,
                            const int* __restrict__ init_tok,
                            const float* __restrict__ hidden) {
    const bool is64 = tok_is64(targets);
    int t = blockIdx.x * blockDim.x + threadIdx.x;
    int nt = gridDim.x * blockDim.x;
    for (int i = t; i < 128 * 32; i += nt) g_arr[i] = 0u;
    if (t < NTOK) {
        int s = t >> 5, b = t & 31;
        g_tok[t] = (s == 0) ? init_tok[0]
                            : tok_at(targets, b * SEQ + (s - 1), is64);
    }
    for (int i = t; i < BSZ * HID; i += nt)
        g_h[0][i] = hidden[i];
}

// ---------------- pre-convert W_out to fp16 (RN); PDL primary ------------
__global__ void conv_w(const float* __restrict__ W) {
    // let gemm_xg (independent) launch and run concurrently
    asm volatile("griddepcontrol.launch_dependents;" ::: "memory");
    int t = blockIdx.x * blockDim.x + threadIdx.x;
    int nt = gridDim.x * blockDim.x;
    const int n4 = (VOC * HID) / 4;
    for (int i = t; i < n4; i += nt) {
        float4 v = ((const float4*)W)[i];
        __half2 h01 = __floats2half2_rn(v.x, v.y);
        __half2 h23 = __floats2half2_rn(v.z, v.w);
        *(__half2*)(g_wout_h + (size_t)i * 4)     = h01;
        *(__half2*)(g_wout_h + (size_t)i * 4 + 2) = h23;
    }
}

// ---------------- x_gates GEMM (embedding gather, tf32 mma.sync) ---------
__global__ void __launch_bounds__(256, 2)
gemm_xg(const float* __restrict__ A, const float* __restrict__ Bm,
        const float* __restrict__ bias) {
    __shared__ unsigned As[128 * 36];
    __shared__ unsigned Bs[128 * 36];

    const int tid  = threadIdx.x;
    const int n0   = blockIdx.x * 128;
    const int m0   = blockIdx.y * 128;
    const int lane = tid & 31, warp = tid >> 5;
    const int wm = warp & 1, wn = warp >> 1;
    const int g  = lane >> 2, tg = lane & 3;

    const float* aptr[4];
    const float* bptr[4];
    int soff[4];
#pragma unroll
    for (int i = 0; i < 4; ++i) {
        int idx = tid + i * 256;
        int row = idx >> 3, cv = idx & 7;
        int arow = g_tok[m0 + row];
        aptr[i] = A + (size_t)arow * HID + cv * 4;
        bptr[i] = Bm + (size_t)(n0 + row) * HID + cv * 4;
        soff[i] = row * 36 + cv * 4;
    }

    float c[4][4][4];
#pragma unroll
    for (int a = 0; a < 4; ++a)
#pragma unroll
        for (int b = 0; b < 4; ++b)
#pragma unroll
            for (int k = 0; k < 4; ++k) c[a][b][k] = 0.f;

    for (int kt = 0; kt < 16; ++kt) {
        float4 va[4], vb[4];
#pragma unroll
        for (int i = 0; i < 4; ++i) {
            va[i] = *(const float4*)(aptr[i] + kt * 32);
            vb[i] = *(const float4*)(bptr[i] + kt * 32);
        }
        __syncthreads();
#pragma unroll
        for (int i = 0; i < 4; ++i) {
            As[soff[i] + 0] = f2tf(va[i].x); As[soff[i] + 1] = f2tf(va[i].y);
            As[soff[i] + 2] = f2tf(va[i].z); As[soff[i] + 3] = f2tf(va[i].w);
            Bs[soff[i] + 0] = f2tf(vb[i].x); Bs[soff[i] + 1] = f2tf(vb[i].y);
            Bs[soff[i] + 2] = f2tf(vb[i].z); Bs[soff[i] + 3] = f2tf(vb[i].w);
        }
        __syncthreads();

#pragma unroll
        for (int kk = 0; kk < 4; ++kk) {
            const int kb = kk * 8;
            unsigned afr[4][4], bfr[4][2];
#pragma unroll
            for (int mf = 0; mf < 4; ++mf) {
                int r0 = (wm * 64 + mf * 16 + g) * 36 + kb + tg;
                afr[mf][0] = As[r0];
                afr[mf][1] = As[r0 + 8 * 36];
                afr[mf][2] = As[r0 + 4];
                afr[mf][3] = As[r0 + 8 * 36 + 4];
            }
#pragma unroll
            for (int nf = 0; nf < 4; ++nf) {
                int r0 = (wn * 32 + nf * 8 + g) * 36 + kb + tg;
                bfr[nf][0] = Bs[r0];
                bfr[nf][1] = Bs[r0 + 4];
            }
#pragma unroll
            for (int mf = 0; mf < 4; ++mf)
#pragma unroll
                for (int nf = 0; nf < 4; ++nf)
                    mma8(c[mf][nf], afr[mf], bfr[nf][0], bfr[nf][1]);
        }
    }

#pragma unroll
    for (int mf = 0; mf < 4; ++mf) {
#pragma unroll
        for (int nf = 0; nf < 4; ++nf) {
            int row = m0 + wm * 64 + mf * 16 + g;
            int col = n0 + wn * 32 + nf * 8 + 2 * tg;
            float b0v = bias[col], b1v = bias[col + 1];
            float2 v0 = make_float2(c[mf][nf][0] + b0v, c[mf][nf][1] + b1v);
            float2 v1 = make_float2(c[mf][nf][2] + b0v, c[mf][nf][3] + b1v);
            *(float2*)&g_xg[(size_t)row * NGATE + col]       = v0;
            *(float2*)&g_xg[(size_t)(row + 8) * NGATE + col] = v1;
        }
    }
}

// ---------------- logits GEMM: fp16 m16n8k16, K=32 chunks, 4 stages ------
#define GKH   32            /* halves per chunk */
#define NCHH  16            /* 512 / 32 */
#define RSB   96            /* bytes per row in smem */
#define AWB   (128 * RSB)   /* 12288 B per A stage */
#define STWB  (2 * AWB)     /* 24576 B per stage */
#define NSTG  4
#define SMEMH (NSTG * STWB) /* 98304 B */

__global__ void __launch_bounds__(256, 2)
gemm3(const float* __restrict__ bias, float* __restrict__ out) {
    // ---- PDL gate: wait until the scan has produced this tile's rows ----
    {
        const unsigned need = (unsigned)(blockIdx.y * 4 + 4);
        if (threadIdx.x < 32) {
            for (;;) {
                unsigned ok = 1;
#pragma unroll
                for (int i = 0; i < 4; ++i) {
                    unsigned v;
                    asm volatile("ld.acquire.gpu.global.u32 %0, [%1];"
                                 : "=r"(v)
                                 : "l"(&g_arr[(threadIdx.x * 4 + i) * 32])
                                 : "memory");
                    ok &= (v >= need) ? 1u : 0u;
                }
                if (__all_sync(0xffffffffu, ok)) break;
                __nanosleep(256);
            }
        }
        __syncthreads();
    }

    extern __shared__ char smemc[];
    const uint32_t sb = s2u(smemc);
    const int tid  = threadIdx.x;
    const int wid  = tid >> 5, lane = tid & 31;
    const int wm = wid & 1, wn = wid >> 1;         // 2 x 4 warps
    const int g  = lane >> 2, tg = lane & 3;
    const int n0 = blockIdx.x * 128, m0 = blockIdx.y * 128;

    const __half* asrc[2]; uint32_t adst[2];
    const __half* bsrc[2]; uint32_t bdst[2];
#pragma unroll
    for (int i = 0; i < 2; ++i) {
        int idx = tid + i * 256, r = idx >> 2, c4 = idx & 3;
        asrc[i] = g_hs_h + (size_t)(m0 + r) * HID + c4 * 8;
        adst[i] = (uint32_t)(r * RSB + c4 * 16);
        bsrc[i] = g_wout_h + (size_t)(n0 + r) * HID + c4 * 8;
        bdst[i] = (uint32_t)(AWB + r * RSB + c4 * 16);
    }

    float c[4][4][4];
#pragma unroll
    for (int mf = 0; mf < 4; ++mf)
#pragma unroll
        for (int nf = 0; nf < 4; ++nf)
#pragma unroll
            for (int k = 0; k < 4; ++k) c[mf][nf][k] = 0.f;

#pragma unroll
    for (int pc = 0; pc < 3; ++pc) {      // prologue: chunks 0..2
        uint32_t sbase = sb + (uint32_t)(pc * STWB);
        int kb = pc * GKH;
#pragma unroll
        for (int i = 0; i < 2; ++i) {
            asm volatile("cp.async.cg.shared.global [%0], [%1], 16;"
                         :: "r"(sbase + adst[i]), "l"(asrc[i] + kb) : "memory");
            asm volatile("cp.async.cg.shared.global [%0], [%1], 16;"
                         :: "r"(sbase + bdst[i]), "l"(bsrc[i] + kb) : "memory");
        }
        asm volatile("cp.async.commit_group;" ::: "memory");
    }

#pragma unroll 1
    for (int ch = 0; ch < NCHH; ++ch) {
        asm volatile("cp.async.wait_group 2;" ::: "memory");  // chunk ch done
        __syncthreads();   // also: stage (ch+3)%4 fully read at iter ch-1

        {   // issue chunk ch+3 into stage (ch+3)%4
            int nc = ch + 3;
            if (nc < NCHH) {
                uint32_t sbase = sb + (uint32_t)((nc % NSTG) * STWB);
                int kb = nc * GKH;
#pragma unroll
                for (int i = 0; i < 2; ++i) {
                    asm volatile("cp.async.cg.shared.global [%0], [%1], 16;"
                                 :: "r"(sbase + adst[i]), "l"(asrc[i] + kb)
                                 : "memory");
                    asm volatile("cp.async.cg.shared.global [%0], [%1], 16;"
                                 :: "r"(sbase + bdst[i]), "l"(bsrc[i] + kb)
                                 : "memory");
                }
            }
            asm volatile("cp.async.commit_group;" ::: "memory");
        }

        const uint32_t sbase = sb + (uint32_t)((ch % NSTG) * STWB);
#pragma unroll
        for (int kk = 0; kk < 2; ++kk) {       // two k16 slices per chunk
            uint32_t a[4][4];
#pragma unroll
            for (int mf = 0; mf < 4; ++mf) {
                int r0 = wm * 64 + mf * 16 + g;
                uint32_t ad0 = sbase + (uint32_t)(r0 * RSB + kk * 32 + tg * 8);
                uint32_t ad1 = sbase +
                    (uint32_t)((r0 + 8) * RSB + kk * 32 + tg * 8);
                asm volatile("ld.shared.v2.b32 {%0,%1}, [%2];"
                             : "=r"(a[mf][0]), "=r"(a[mf][2]) : "r"(ad0));
                asm volatile("ld.shared.v2.b32 {%0,%1}, [%2];"
                             : "=r"(a[mf][1]), "=r"(a[mf][3]) : "r"(ad1));
            }
#pragma unroll
            for (int nf = 0; nf < 4; ++nf) {
                int rn = wn * 32 + nf * 8 + g;
                uint32_t bd = sbase +
                    (uint32_t)(AWB + rn * RSB + kk * 32 + tg * 8);
                uint32_t b0, b1;
                asm volatile("ld.shared.v2.b32 {%0,%1}, [%2];"
                             : "=r"(b0), "=r"(b1) : "r"(bd));
#pragma unroll
                for (int mf = 0; mf < 4; ++mf)
                    mma16h(c[mf][nf], a[mf][0], a[mf][1], a[mf][2], a[mf][3],
                           b0, b1);
            }
        }
    }

    // epilogue: rows -> (s,b) remap, add bias
#pragma unroll
    for (int mf = 0; mf < 4; ++mf) {
        int row = m0 + wm * 64 + mf * 16 + g;
        int s0 = row >> 5, b0i = row & 31;
        int r1 = row + 8;
        int s1 = r1 >> 5, b1i = r1 & 31;
        float* o0 = out + ((size_t)b0i * SEQ + s0) * VOC;
        float* o1 = out + ((size_t)b1i * SEQ + s1) * VOC;
#pragma unroll
        for (int nf = 0; nf < 4; ++nf) {
            int col = n0 + wn * 32 + nf * 8 + 2 * tg;
            float bv0 = bias[col], bv1 = bias[col + 1];
            *(float2*)(o0 + col) = make_float2(c[mf][nf][0] + bv0,
                                               c[mf][nf][1] + bv1);
            *(float2*)(o1 + col) = make_float2(c[mf][nf][2] + bv0,
                                               c[mf][nf][3] + bv1);
        }
    }
}

// ---------------- persistent GRU scan: 32 j-groups x 4 batch-groups ------
// Epilogue distributed across 8 lanes per k-group (butterfly leaves full
// sums in every lane) -> 8 parallel activation chains instead of 1 serial.
#define RS_H   0
#define RS_W   4096
#define RS_BI  (RS_W + 48 * HID)
#define RS_XG  (RS_BI + 48)
#define RS_TOT ((RS_XG + 384) * 4)     /* 116416 B */

__global__ void __launch_bounds__(256, 2)
recur_kernel(const float* __restrict__ W_hh, const float* __restrict__ b_hh) {
    // allow the dependent logits GEMM to start launching now
    asm volatile("griddepcontrol.launch_dependents;" ::: "memory");

    extern __shared__ float sm[];
    float* h_sm    = sm + RS_H;
    float* w_sm    = sm + RS_W;
    float* bias_sm = sm + RS_BI;
    float* xg_sm   = sm + RS_XG;
    const uint32_t sb = s2u(sm);

    const int tid = threadIdx.x;
    const int bg  = blockIdx.x & 3;
    const int jg  = blockIdx.x >> 2;
    const int j0  = jg * 16;
    const int bbase = bg * 8;

    // load W slice: 48 rows (16 local j x 3 gates) x 512
    for (int i = tid; i < 48 * HID; i += 256) {
        int r = i >> 9, k = i & 511;
        int lj = r / 3, gg = r % 3;
        w_sm[i] = W_hh[(size_t)(gg * HID + j0 + lj) * HID + k];
    }
    if (tid < 48) {
        int lj = tid / 3, gg = tid % 3;
        bias_sm[tid] = b_hh[gg * HID + j0 + lj];
    }

    const int ks = tid & 15;          // 16-way k split
    const int grp = tid >> 4;         // 16 (bq, jl) groups
    const int bq = grp & 1;           // 2 batch quads (4 b each)
    const int jl = grp >> 1;          // 8 j-pairs: lj = jl*2 + jj
    const float* wp[6];               // [jj*3 + gate]
#pragma unroll
    for (int jj = 0; jj < 2; ++jj)
#pragma unroll
        for (int gg = 0; gg < 3; ++gg)
            wp[jj * 3 + gg] = w_sm + ((jl * 2 + jj) * 3 + gg) * HID;

    // xg staging (tid < 96): 8 b x 3 gates x 4 quarters of 4 j
    const int xbl = tid / 12, xrem = tid - xbl * 12;
    const int xgt = xrem >> 2, xq = xrem & 3;
    const uint32_t xg_dst =
        sb + (uint32_t)((RS_XG + xbl * 48 + xgt * 16 + xq * 4) * 4);
    const float* xg_srcb =
        g_xg + (size_t)(bbase + xbl) * NGATE + xgt * HID + j0 + xq * 4;

    __syncthreads();

    for (int s = 0; s < SEQ; ++s) {
        // stage xg[s] slice (independent of h)
        if (tid < 96) {
            const float* src = xg_srcb + (size_t)s * BSZ * NGATE;
            asm volatile("cp.async.cg.shared.global [%0], [%1], 16;"
                         :: "r"(xg_dst), "l"(src) : "memory");
        }
        // broadcast own batch column's h (8 x 512 = 16KB) into smem
        {
            const float* src = g_h[s & 1] + bbase * HID;
#pragma unroll
            for (int t = 0; t < 4; ++t) {
                int idx = tid + t * 256;
                asm volatile("cp.async.cg.shared.global [%0], [%1], 16;"
                             :: "r"(sb + (uint32_t)((RS_H + idx * 4) * 4)),
                                "l"(src + idx * 4) : "memory");
            }
        }
        asm volatile("cp.async.commit_group;" ::: "memory");
        asm volatile("cp.async.wait_group 0;" ::: "memory");
        __syncthreads();

        unsigned long long acc[6][4];   // [jj*3+gate][bi]
#pragma unroll
        for (int q = 0; q < 6; ++q)
#pragma unroll
            for (int bi = 0; bi < 4; ++bi) acc[q][bi] = 0ull;

#pragma unroll
        for (int i = 0; i < 8; ++i) {
            int k = ks * 4 + i * 64;
            ulonglong2 w2[6];
#pragma unroll
            for (int q = 0; q < 6; ++q)
                w2[q] = *(const ulonglong2*)(wp[q] + k);
#pragma unroll
            for (int bi = 0; bi < 4; ++bi) {
                int bl = bq * 4 + bi;
                ulonglong2 h2 = *(const ulonglong2*)(h_sm + bl * HID + k);
#pragma unroll
                for (int q = 0; q < 6; ++q) {
                    fma2(acc[q][bi], h2.x, w2[q].x);
                    fma2(acc[q][bi], h2.y, w2[q].y);
                }
            }
        }
        float a[6][4];
#pragma unroll
        for (int q = 0; q < 6; ++q)
#pragma unroll
            for (int bi = 0; bi < 4; ++bi) a[q][bi] = pairsum(acc[q][bi]);
        // full butterfly: every one of the 16 k-lanes ends with the sums
#pragma unroll
        for (int off = 8; off > 0; off >>= 1) {
#pragma unroll
            for (int q = 0; q < 6; ++q)
#pragma unroll
                for (int bi = 0; bi < 4; ++bi)
                    a[q][bi] += __shfl_xor_sync(0xffffffffu, a[q][bi], off);
        }
        // distributed epilogue: lane ks<8 handles output (jj = ks>>2,
        // bi = ks&3) -> 8 parallel activation chains per group
        if (ks < 8) {
            int jj = ks >> 2;
            int bi = ks & 3;
            int lj = jl * 2 + jj;
            int j  = j0 + lj;
            int bl = bq * 4 + bi;
            int b  = bbase + bl;
            float br = bias_sm[lj * 3 + 0];
            float bz = bias_sm[lj * 3 + 1];
            float bn = bias_sm[lj * 3 + 2];
            float rr = fsigm(xg_sm[bl * 48 + 0  + lj] + a[jj * 3 + 0][bi] + br);
            float zz = fsigm(xg_sm[bl * 48 + 16 + lj] + a[jj * 3 + 1][bi] + bz);
            float nn = ftanh(xg_sm[bl * 48 + 32 + lj] +
                             rr * (a[jj * 3 + 2][bi] + bn));
            float hold = h_sm[bl * HID + j];
            float hnew = (1.f - zz) * nn + zz * hold;
            g_h[(s + 1) & 1][b * HID + j] = hnew;
            g_hs_h[(size_t)(s * BSZ + b) * HID + j] = __float2half_rn(hnew);
        }
        if (s == SEQ - 1) break;

        // ---- column barrier: store-arrive + poll own 32 CTAs ----
        __syncthreads();
        const unsigned sv = (unsigned)(s + 1);
        if (tid == 0) {
            asm volatile("st.release.gpu.global.u32 [%0], %1;"
                         :: "l"(&g_arr[blockIdx.x * 32]), "r"(sv) : "memory");
        }
        if (tid < 32) {
            int cc = tid * 4 + bg;     // same-column CTA ids
            for (;;) {
                unsigned v;
                asm volatile("ld.acquire.gpu.global.u32 %0, [%1];"
                             : "=r"(v) : "l"(&g_arr[cc * 32]) : "memory");
                if (__all_sync(0xffffffffu, (v >= sv) ? 1u : 0u)) break;
            }
        }
        __syncthreads();
    }

    // final arrival: publish step 128 (releases last M-tiles to gemm3)
    __syncthreads();
    if (tid == 0) {
        asm volatile("st.release.gpu.global.u32 [%0], %1;"
                     :: "l"(&g_arr[blockIdx.x * 32]), "r"((unsigned)SEQ)
                     : "memory");
    }
}

// ---------------- launch ----------------
extern "C" void kernel_launch(void* const* d_in, const int* in_sizes, int n_in,
                              void* d_out, int out_size) {
    const float* hidden    = (const float*)d_in[0];
    const void*  targets   = (const void*)d_in[1];
    const float* embedding = (const float*)d_in[2];
    const float* W_ih      = (const float*)d_in[3];
    const float* W_hh      = (const float*)d_in[4];
    const float* b_ih      = (const float*)d_in[5];
    const float* b_hh      = (const float*)d_in[6];
    const float* W_out     = (const float*)d_in[7];
    const float* b_out     = (const float*)d_in[8];
    const int*   init_tok  = (const int*)d_in[9];
    float*       out       = (float*)d_out;

    cudaFuncSetAttribute(recur_kernel,
                         cudaFuncAttributeMaxDynamicSharedMemorySize, RS_TOT);
    cudaFuncSetAttribute(gemm3,
                         cudaFuncAttributeMaxDynamicSharedMemorySize, SMEMH);
    // matching smem carveout configs -> CTAs of both kernels can co-locate
    cudaFuncSetAttribute(recur_kernel,
                         cudaFuncAttributePreferredSharedMemoryCarveout, 100);
    cudaFuncSetAttribute(gemm3,
                         cudaFuncAttributePreferredSharedMemoryCarveout, 100);

    init_kernel<<<16, 256>>>(targets, init_tok, hidden);

    // W_out fp16 conversion (PDL primary) overlapped with x_gates GEMM
    conv_w<<<256, 256>>>(W_out);
    {
        cudaLaunchConfig_t cfg = {};
        cfg.gridDim  = dim3(NGATE / 128, NTOK / 128);
        cfg.blockDim = dim3(256);
        cudaLaunchAttribute attr[1];
        attr[0].id = cudaLaunchAttributeProgrammaticStreamSerialization;
        attr[0].val.programmaticStreamSerializationAllowed = 1;
        cfg.attrs = attr;
        cfg.numAttrs = 1;
        cudaLaunchKernelEx(&cfg, gemm_xg, (const float*)embedding,
                           (const float*)W_ih, (const float*)b_ih);
    }

    // sequential GRU scan (persistent, 128 co-resident CTAs)
    recur_kernel<<<128, 256, RS_TOT>>>(W_hh, b_hh);

    // logits GEMM (fp16, 4-stage), PDL-overlapped with the scan
    {
        cudaLaunchConfig_t cfg = {};
        cfg.gridDim  = dim3(VOC / 128, NTOK / 128);
        cfg.blockDim = dim3(256);
        cfg.dynamicSmemBytes = SMEMH;
        cudaLaunchAttribute attr[1];
        attr[0].id = cudaLaunchAttributeProgrammaticStreamSerialization;
        attr[0].val.programmaticStreamSerializationAllowed = 1;
        cfg.attrs = attr;
        cfg.numAttrs = 1;
        cudaLaunchKernelEx(&cfg, gemm3, (const float*)b_out, out);
    }
}

// round 17
// speedup vs baseline: 1.2322x; 1.0024x over previous
#include <cuda_runtime.h>
#include <cuda_fp16.h>
#include <cstdint>
#include <cmath>

#define BSZ   32
#define SEQ   128
#define HID   512
#define NGATE 1536
#define VOC   32000
#define NTOK  4096   /* BSZ*SEQ */

// ---------------- device scratch (no allocations allowed) ----------------
__device__ int      g_tok[NTOK];
__device__ float    g_xg[(size_t)NTOK * NGATE];    // [S][B][3H], b_ih folded in
__device__ __half   g_hs_h[(size_t)NTOK * HID];    // fp16 hidden states
__device__ __half   g_wout_h[(size_t)VOC * HID];   // fp16 W_out
__device__ float    g_h[2][BSZ * HID];             // ping-pong hidden state
__device__ unsigned g_arr[128 * 32];               // per-CTA arrival slots (128B apart)

__device__ __forceinline__ unsigned f2tf(float x) {
    unsigned r;
    asm("cvt.rna.tf32.f32 %0, %1;" : "=r"(r) : "f"(x));
    return r;
}
__device__ __forceinline__ uint32_t s2u(const void* p) {
    uint32_t a;
    asm("{ .reg .u64 t; cvta.to.shared.u64 t, %1; cvt.u32.u64 %0, t; }"
        : "=r"(a) : "l"(p));
    return a;
}
// packed fp32x2 FMA: d = a*b + d  (two exact fp32 FMAs in one instruction)
__device__ __forceinline__ void fma2(unsigned long long& d,
                                     unsigned long long a,
                                     unsigned long long b) {
    asm("fma.rn.f32x2 %0, %1, %2, %0;" : "+l"(d) : "l"(a), "l"(b));
}
__device__ __forceinline__ float pairsum(unsigned long long v) {
    unsigned lo, hi;
    asm("mov.b64 {%0, %1}, %2;" : "=r"(lo), "=r"(hi) : "l"(v));
    return __uint_as_float(lo) + __uint_as_float(hi);
}

// targets may be int32 (JAX x64 disabled) or int64. Detect: int64 tokens
// always have zero high words -> first 8 int64 views all in [0, VOC).
__device__ __forceinline__ bool tok_is64(const void* p) {
    const long long* q = (const long long*)p;
    bool ok = true;
#pragma unroll
    for (int i = 0; i < 8; ++i) {
        long long v = q[i];
        ok = ok && (v >= 0) && (v < VOC);
    }
    return ok;
}
__device__ __forceinline__ int tok_at(const void* p, int idx, bool is64) {
    return is64 ? (int)((const long long*)p)[idx] : ((const int*)p)[idx];
}

__device__ __forceinline__ float fsigm(float x) {
    return __fdividef(1.f, 1.f + __expf(-x));
}
__device__ __forceinline__ float ftanh(float x) {
    float ax = fabsf(x);
    float e  = __expf(-2.f * ax);
    float t  = __fdividef(1.f - e, 1.f + e);
    return copysignf(t, x);
}

__device__ __forceinline__ void mma8(float* c, const uint32_t* a,
                                     uint32_t b0, uint32_t b1) {
    asm volatile(
        "mma.sync.aligned.m16n8k8.row.col.f32.tf32.tf32.f32 "
        "{%0,%1,%2,%3}, {%4,%5,%6,%7}, {%8,%9}, {%0,%1,%2,%3};"
        : "+f"(c[0]), "+f"(c[1]), "+f"(c[2]), "+f"(c[3])
        : "r"(a[0]), "r"(a[1]), "r"(a[2]), "r"(a[3]), "r"(b0), "r"(b1));
}
__device__ __forceinline__ void mma16h(float* c, uint32_t a0, uint32_t a1,
                                       uint32_t a2, uint32_t a3,
                                       uint32_t b0, uint32_t b1) {
    asm volatile(
        "mma.sync.aligned.m16n8k16.row.col.f32.f16.f16.f32 "
        "{%0,%1,%2,%3}, {%4,%5,%6,%7}, {%8,%9}, {%0,%1,%2,%3};"
        : "+f"(c[0]), "+f"(c[1]), "+f"(c[2]), "+f"(c[3])
        : "r"(a0), "r"(a1), "r"(a2), "r"(a3), "r"(b0), "r"(b1));
}

// ---------------- init: token indices, h0, barrier reset -----------------
__global__ void init_kernel(const void* __restrict__ targets,
                            const int* __restrict__ init_tok,
                            const float* __restrict__ hidden) {
    const bool is64 = tok_is64(targets);
    int t = blockIdx.x * blockDim.x + threadIdx.x;
    int nt = gridDim.x * blockDim.x;
    for (int i = t; i < 128 * 32; i += nt) g_arr[i] = 0u;
    if (t < NTOK) {
        int s = t >> 5, b = t & 31;
        g_tok[t] = (s == 0) ? init_tok[0]
                            : tok_at(targets, b * SEQ + (s - 1), is64);
    }
    for (int i = t; i < BSZ * HID; i += nt)
        g_h[0][i] = hidden[i];
}

// ---------------- pre-convert W_out to fp16 (RN); PDL primary ------------
__global__ void conv_w(const float* __restrict__ W) {
    // let gemm_xg (independent) launch and run concurrently
    asm volatile("griddepcontrol.launch_dependents;" ::: "memory");
    int t = blockIdx.x * blockDim.x + threadIdx.x;
    int nt = gridDim.x * blockDim.x;
    const int n4 = (VOC * HID) / 4;
    for (int i = t; i < n4; i += nt) {
        float4 v = ((const float4*)W)[i];
        __half2 h01 = __floats2half2_rn(v.x, v.y);
        __half2 h23 = __floats2half2_rn(v.z, v.w);
        *(__half2*)(g_wout_h + (size_t)i * 4)     = h01;
        *(__half2*)(g_wout_h + (size_t)i * 4 + 2) = h23;
    }
}

// ---------------- x_gates GEMM (embedding gather, tf32 mma.sync) ---------
__global__ void __launch_bounds__(256, 2)
gemm_xg(const float* __restrict__ A, const float* __restrict__ Bm,
        const float* __restrict__ bias) {
    __shared__ unsigned As[128 * 36];
    __shared__ unsigned Bs[128 * 36];

    const int tid  = threadIdx.x;
    const int n0   = blockIdx.x * 128;
    const int m0   = blockIdx.y * 128;
    const int lane = tid & 31, warp = tid >> 5;
    const int wm = warp & 1, wn = warp >> 1;
    const int g  = lane >> 2, tg = lane & 3;

    const float* aptr[4];
    const float* bptr[4];
    int soff[4];
#pragma unroll
    for (int i = 0; i < 4; ++i) {
        int idx = tid + i * 256;
        int row = idx >> 3, cv = idx & 7;
        int arow = g_tok[m0 + row];
        aptr[i] = A + (size_t)arow * HID + cv * 4;
        bptr[i] = Bm + (size_t)(n0 + row) * HID + cv * 4;
        soff[i] = row * 36 + cv * 4;
    }

    float c[4][4][4];
#pragma unroll
    for (int a = 0; a < 4; ++a)
#pragma unroll
        for (int b = 0; b < 4; ++b)
#pragma unroll
            for (int k = 0; k < 4; ++k) c[a][b][k] = 0.f;

    for (int kt = 0; kt < 16; ++kt) {
        float4 va[4], vb[4];
#pragma unroll
        for (int i = 0; i < 4; ++i) {
            va[i] = *(const float4*)(aptr[i] + kt * 32);
            vb[i] = *(const float4*)(bptr[i] + kt * 32);
        }
        __syncthreads();
#pragma unroll
        for (int i = 0; i < 4; ++i) {
            As[soff[i] + 0] = f2tf(va[i].x); As[soff[i] + 1] = f2tf(va[i].y);
            As[soff[i] + 2] = f2tf(va[i].z); As[soff[i] + 3] = f2tf(va[i].w);
            Bs[soff[i] + 0] = f2tf(vb[i].x); Bs[soff[i] + 1] = f2tf(vb[i].y);
            Bs[soff[i] + 2] = f2tf(vb[i].z); Bs[soff[i] + 3] = f2tf(vb[i].w);
        }
        __syncthreads();

#pragma unroll
        for (int kk = 0; kk < 4; ++kk) {
            const int kb = kk * 8;
            unsigned afr[4][4], bfr[4][2];
#pragma unroll
            for (int mf = 0; mf < 4; ++mf) {
                int r0 = (wm * 64 + mf * 16 + g) * 36 + kb + tg;
                afr[mf][0] = As[r0];
                afr[mf][1] = As[r0 + 8 * 36];
                afr[mf][2] = As[r0 + 4];
                afr[mf][3] = As[r0 + 8 * 36 + 4];
            }
#pragma unroll
            for (int nf = 0; nf < 4; ++nf) {
                int r0 = (wn * 32 + nf * 8 + g) * 36 + kb + tg;
                bfr[nf][0] = Bs[r0];
                bfr[nf][1] = Bs[r0 + 4];
            }
#pragma unroll
            for (int mf = 0; mf < 4; ++mf)
#pragma unroll
                for (int nf = 0; nf < 4; ++nf)
                    mma8(c[mf][nf], afr[mf], bfr[nf][0], bfr[nf][1]);
        }
    }

#pragma unroll
    for (int mf = 0; mf < 4; ++mf) {
#pragma unroll
        for (int nf = 0; nf < 4; ++nf) {
            int row = m0 + wm * 64 + mf * 16 + g;
            int col = n0 + wn * 32 + nf * 8 + 2 * tg;
            float b0v = bias[col], b1v = bias[col + 1];
            float2 v0 = make_float2(c[mf][nf][0] + b0v, c[mf][nf][1] + b1v);
            float2 v1 = make_float2(c[mf][nf][2] + b0v, c[mf][nf][3] + b1v);
            *(float2*)&g_xg[(size_t)row * NGATE + col]       = v0;
            *(float2*)&g_xg[(size_t)(row + 8) * NGATE + col] = v1;
        }
    }
}

// ---------------- logits GEMM: fp16 m16n8k16, K=32 chunks, 4 stages ------
#define GKH   32            /* halves per chunk */
#define NCHH  16            /* 512 / 32 */
#define RSB   96            /* bytes per row in smem */
#define AWB   (128 * RSB)   /* 12288 B per A stage */
#define STWB  (2 * AWB)     /* 24576 B per stage */
#define NSTG  4
#define SMEMH (NSTG * STWB) /* 98304 B */

__global__ void __launch_bounds__(256, 2)
gemm3(const float* __restrict__ bias, float* __restrict__ out) {
    // ---- PDL gate: wait until the scan has produced this tile's rows ----
    {
        const unsigned need = (unsigned)(blockIdx.y * 4 + 4);
        if (threadIdx.x < 32) {
            for (;;) {
                unsigned ok = 1;
#pragma unroll
                for (int i = 0; i < 4; ++i) {
                    unsigned v;
                    asm volatile("ld.acquire.gpu.global.u32 %0, [%1];"
                                 : "=r"(v)
                                 : "l"(&g_arr[(threadIdx.x * 4 + i) * 32])
                                 : "memory");
                    ok &= (v >= need) ? 1u : 0u;
                }
                if (__all_sync(0xffffffffu, ok)) break;
                __nanosleep(256);
            }
        }
        __syncthreads();
    }

    extern __shared__ char smemc[];
    const uint32_t sb = s2u(smemc);
    const int tid  = threadIdx.x;
    const int wid  = tid >> 5, lane = tid & 31;
    const int wm = wid & 1, wn = wid >> 1;         // 2 x 4 warps
    const int g  = lane >> 2, tg = lane & 3;
    const int n0 = blockIdx.x * 128, m0 = blockIdx.y * 128;

    const __half* asrc[2]; uint32_t adst[2];
    const __half* bsrc[2]; uint32_t bdst[2];
#pragma unroll
    for (int i = 0; i < 2; ++i) {
        int idx = tid + i * 256, r = idx >> 2, c4 = idx & 3;
        asrc[i] = g_hs_h + (size_t)(m0 + r) * HID + c4 * 8;
        adst[i] = (uint32_t)(r * RSB + c4 * 16);
        bsrc[i] = g_wout_h + (size_t)(n0 + r) * HID + c4 * 8;
        bdst[i] = (uint32_t)(AWB + r * RSB + c4 * 16);
    }

    float c[4][4][4];
#pragma unroll
    for (int mf = 0; mf < 4; ++mf)
#pragma unroll
        for (int nf = 0; nf < 4; ++nf)
#pragma unroll
            for (int k = 0; k < 4; ++k) c[mf][nf][k] = 0.f;

#pragma unroll
    for (int pc = 0; pc < 3; ++pc) {      // prologue: chunks 0..2
        uint32_t sbase = sb + (uint32_t)(pc * STWB);
        int kb = pc * GKH;
#pragma unroll
        for (int i = 0; i < 2; ++i) {
            asm volatile("cp.async.cg.shared.global [%0], [%1], 16;"
                         :: "r"(sbase + adst[i]), "l"(asrc[i] + kb) : "memory");
            asm volatile("cp.async.cg.shared.global [%0], [%1], 16;"
                         :: "r"(sbase + bdst[i]), "l"(bsrc[i] + kb) : "memory");
        }
        asm volatile("cp.async.commit_group;" ::: "memory");
    }

#pragma unroll 1
    for (int ch = 0; ch < NCHH; ++ch) {
        asm volatile("cp.async.wait_group 2;" ::: "memory");  // chunk ch done
        __syncthreads();   // also: stage (ch+3)%4 fully read at iter ch-1

        {   // issue chunk ch+3 into stage (ch+3)%4
            int nc = ch + 3;
            if (nc < NCHH) {
                uint32_t sbase = sb + (uint32_t)((nc % NSTG) * STWB);
                int kb = nc * GKH;
#pragma unroll
                for (int i = 0; i < 2; ++i) {
                    asm volatile("cp.async.cg.shared.global [%0], [%1], 16;"
                                 :: "r"(sbase + adst[i]), "l"(asrc[i] + kb)
                                 : "memory");
                    asm volatile("cp.async.cg.shared.global [%0], [%1], 16;"
                                 :: "r"(sbase + bdst[i]), "l"(bsrc[i] + kb)
                                 : "memory");
                }
            }
            asm volatile("cp.async.commit_group;" ::: "memory");
        }

        const uint32_t sbase = sb + (uint32_t)((ch % NSTG) * STWB);
#pragma unroll
        for (int kk = 0; kk < 2; ++kk) {       // two k16 slices per chunk
            uint32_t a[4][4];
#pragma unroll
            for (int mf = 0; mf < 4; ++mf) {
                int r0 = wm * 64 + mf * 16 + g;
                uint32_t ad0 = sbase + (uint32_t)(r0 * RSB + kk * 32 + tg * 8);
                uint32_t ad1 = sbase +
                    (uint32_t)((r0 + 8) * RSB + kk * 32 + tg * 8);
                asm volatile("ld.shared.v2.b32 {%0,%1}, [%2];"
                             : "=r"(a[mf][0]), "=r"(a[mf][2]) : "r"(ad0));
                asm volatile("ld.shared.v2.b32 {%0,%1}, [%2];"
                             : "=r"(a[mf][1]), "=r"(a[mf][3]) : "r"(ad1));
            }
#pragma unroll
            for (int nf = 0; nf < 4; ++nf) {
                int rn = wn * 32 + nf * 8 + g;
                uint32_t bd = sbase +
                    (uint32_t)(AWB + rn * RSB + kk * 32 + tg * 8);
                uint32_t b0, b1;
                asm volatile("ld.shared.v2.b32 {%0,%1}, [%2];"
                             : "=r"(b0), "=r"(b1) : "r"(bd));
#pragma unroll
                for (int mf = 0; mf < 4; ++mf)
                    mma16h(c[mf][nf], a[mf][0], a[mf][1], a[mf][2], a[mf][3],
                           b0, b1);
            }
        }
    }

    // epilogue: rows -> (s,b) remap, add bias
#pragma unroll
    for (int mf = 0; mf < 4; ++mf) {
        int row = m0 + wm * 64 + mf * 16 + g;
        int s0 = row >> 5, b0i = row & 31;
        int r1 = row + 8;
        int s1 = r1 >> 5, b1i = r1 & 31;
        float* o0 = out + ((size_t)b0i * SEQ + s0) * VOC;
        float* o1 = out + ((size_t)b1i * SEQ + s1) * VOC;
#pragma unroll
        for (int nf = 0; nf < 4; ++nf) {
            int col = n0 + wn * 32 + nf * 8 + 2 * tg;
            float bv0 = bias[col], bv1 = bias[col + 1];
            *(float2*)(o0 + col) = make_float2(c[mf][nf][0] + bv0,
                                               c[mf][nf][1] + bv1);
            *(float2*)(o1 + col) = make_float2(c[mf][nf][2] + bv0,
                                               c[mf][nf][3] + bv1);
        }
    }
}

// ---------------- persistent GRU scan: 32 j-groups x 4 batch-groups ------
// (R15 epilogue restored: ks==0 handles its group's 8 outputs; the MUFU
// chain is already hidden by 8-way cross-warp parallelism per SMSP)
#define RS_H   0
#define RS_W   4096
#define RS_BI  (RS_W + 48 * HID)
#define RS_XG  (RS_BI + 48)
#define RS_TOT ((RS_XG + 384) * 4)     /* 116416 B */

__global__ void __launch_bounds__(256, 2)
recur_kernel(const float* __restrict__ W_hh, const float* __restrict__ b_hh) {
    // allow the dependent logits GEMM to start launching now
    asm volatile("griddepcontrol.launch_dependents;" ::: "memory");

    extern __shared__ float sm[];
    float* h_sm    = sm + RS_H;
    float* w_sm    = sm + RS_W;
    float* bias_sm = sm + RS_BI;
    float* xg_sm   = sm + RS_XG;
    const uint32_t sb = s2u(sm);

    const int tid = threadIdx.x;
    const int bg  = blockIdx.x & 3;
    const int jg  = blockIdx.x >> 2;
    const int j0  = jg * 16;
    const int bbase = bg * 8;

    // load W slice: 48 rows (16 local j x 3 gates) x 512
    for (int i = tid; i < 48 * HID; i += 256) {
        int r = i >> 9, k = i & 511;
        int lj = r / 3, gg = r % 3;
        w_sm[i] = W_hh[(size_t)(gg * HID + j0 + lj) * HID + k];
    }
    if (tid < 48) {
        int lj = tid / 3, gg = tid % 3;
        bias_sm[tid] = b_hh[gg * HID + j0 + lj];
    }

    const int ks = tid & 15;          // 16-way k split
    const int grp = tid >> 4;         // 16 (bq, jl) groups
    const int bq = grp & 1;           // 2 batch quads (4 b each)
    const int jl = grp >> 1;          // 8 j-pairs: lj = jl*2 + jj
    const float* wp[6];               // [jj*3 + gate]
#pragma unroll
    for (int jj = 0; jj < 2; ++jj)
#pragma unroll
        for (int gg = 0; gg < 3; ++gg)
            wp[jj * 3 + gg] = w_sm + ((jl * 2 + jj) * 3 + gg) * HID;

    // xg staging (tid < 96): 8 b x 3 gates x 4 quarters of 4 j
    const int xbl = tid / 12, xrem = tid - xbl * 12;
    const int xgt = xrem >> 2, xq = xrem & 3;
    const uint32_t xg_dst =
        sb + (uint32_t)((RS_XG + xbl * 48 + xgt * 16 + xq * 4) * 4);
    const float* xg_srcb =
        g_xg + (size_t)(bbase + xbl) * NGATE + xgt * HID + j0 + xq * 4;

    __syncthreads();

    for (int s = 0; s < SEQ; ++s) {
        // stage xg[s] slice (independent of h)
        if (tid < 96) {
            const float* src = xg_srcb + (size_t)s * BSZ * NGATE;
            asm volatile("cp.async.cg.shared.global [%0], [%1], 16;"
                         :: "r"(xg_dst), "l"(src) : "memory");
        }
        // broadcast own batch column's h (8 x 512 = 16KB) into smem
        {
            const float* src = g_h[s & 1] + bbase * HID;
#pragma unroll
            for (int t = 0; t < 4; ++t) {
                int idx = tid + t * 256;
                asm volatile("cp.async.cg.shared.global [%0], [%1], 16;"
                             :: "r"(sb + (uint32_t)((RS_H + idx * 4) * 4)),
                                "l"(src + idx * 4) : "memory");
            }
        }
        asm volatile("cp.async.commit_group;" ::: "memory");
        asm volatile("cp.async.wait_group 0;" ::: "memory");
        __syncthreads();

        unsigned long long acc[6][4];   // [jj*3+gate][bi]
#pragma unroll
        for (int q = 0; q < 6; ++q)
#pragma unroll
            for (int bi = 0; bi < 4; ++bi) acc[q][bi] = 0ull;

#pragma unroll
        for (int i = 0; i < 8; ++i) {
            int k = ks * 4 + i * 64;
            ulonglong2 w2[6];
#pragma unroll
            for (int q = 0; q < 6; ++q)
                w2[q] = *(const ulonglong2*)(wp[q] + k);
#pragma unroll
            for (int bi = 0; bi < 4; ++bi) {
                int bl = bq * 4 + bi;
                ulonglong2 h2 = *(const ulonglong2*)(h_sm + bl * HID + k);
#pragma unroll
                for (int q = 0; q < 6; ++q) {
                    fma2(acc[q][bi], h2.x, w2[q].x);
                    fma2(acc[q][bi], h2.y, w2[q].y);
                }
            }
        }
        float a[6][4];
#pragma unroll
        for (int q = 0; q < 6; ++q)
#pragma unroll
            for (int bi = 0; bi < 4; ++bi) a[q][bi] = pairsum(acc[q][bi]);
        // reduce across the 16 k-split lanes
#pragma unroll
        for (int off = 8; off > 0; off >>= 1) {
#pragma unroll
            for (int q = 0; q < 6; ++q)
#pragma unroll
                for (int bi = 0; bi < 4; ++bi)
                    a[q][bi] += __shfl_xor_sync(0xffffffffu, a[q][bi], off);
        }
        if (ks == 0) {
#pragma unroll
            for (int jj = 0; jj < 2; ++jj) {
                int lj = jl * 2 + jj;
                int j  = j0 + lj;
                float br = bias_sm[lj * 3 + 0];
                float bz = bias_sm[lj * 3 + 1];
                float bn = bias_sm[lj * 3 + 2];
#pragma unroll
                for (int bi = 0; bi < 4; ++bi) {
                    int bl = bq * 4 + bi;
                    int b  = bbase + bl;
                    float rr = fsigm(xg_sm[bl * 48 + 0  + lj] + a[jj * 3 + 0][bi] + br);
                    float zz = fsigm(xg_sm[bl * 48 + 16 + lj] + a[jj * 3 + 1][bi] + bz);
                    float nn = ftanh(xg_sm[bl * 48 + 32 + lj] +
                                     rr * (a[jj * 3 + 2][bi] + bn));
                    float hold = h_sm[bl * HID + j];
                    float hnew = (1.f - zz) * nn + zz * hold;
                    g_h[(s + 1) & 1][b * HID + j] = hnew;
                    g_hs_h[(size_t)(s * BSZ + b) * HID + j] =
                        __float2half_rn(hnew);
                }
            }
        }
        if (s == SEQ - 1) break;

        // ---- column barrier: store-arrive + poll own 32 CTAs ----
        __syncthreads();
        const unsigned sv = (unsigned)(s + 1);
        if (tid == 0) {
            asm volatile("st.release.gpu.global.u32 [%0], %1;"
                         :: "l"(&g_arr[blockIdx.x * 32]), "r"(sv) : "memory");
        }
        if (tid < 32) {
            int cc = tid * 4 + bg;     // same-column CTA ids
            for (;;) {
                unsigned v;
                asm volatile("ld.acquire.gpu.global.u32 %0, [%1];"
                             : "=r"(v) : "l"(&g_arr[cc * 32]) : "memory");
                if (__all_sync(0xffffffffu, (v >= sv) ? 1u : 0u)) break;
            }
        }
        __syncthreads();
    }

    // final arrival: publish step 128 (releases last M-tiles to gemm3)
    __syncthreads();
    if (tid == 0) {
        asm volatile("st.release.gpu.global.u32 [%0], %1;"
                     :: "l"(&g_arr[blockIdx.x * 32]), "r"((unsigned)SEQ)
                     : "memory");
    }
}

// ---------------- launch ----------------
extern "C" void kernel_launch(void* const* d_in, const int* in_sizes, int n_in,
                              void* d_out, int out_size) {
    const float* hidden    = (const float*)d_in[0];
    const void*  targets   = (const void*)d_in[1];
    const float* embedding = (const float*)d_in[2];
    const float* W_ih      = (const float*)d_in[3];
    const float* W_hh      = (const float*)d_in[4];
    const float* b_ih      = (const float*)d_in[5];
    const float* b_hh      = (const float*)d_in[6];
    const float* W_out     = (const float*)d_in[7];
    const float* b_out     = (const float*)d_in[8];
    const int*   init_tok  = (const int*)d_in[9];
    float*       out       = (float*)d_out;

    cudaFuncSetAttribute(recur_kernel,
                         cudaFuncAttributeMaxDynamicSharedMemorySize, RS_TOT);
    cudaFuncSetAttribute(gemm3,
                         cudaFuncAttributeMaxDynamicSharedMemorySize, SMEMH);
    // matching smem carveout configs -> CTAs of both kernels can co-locate
    cudaFuncSetAttribute(recur_kernel,
                         cudaFuncAttributePreferredSharedMemoryCarveout, 100);
    cudaFuncSetAttribute(gemm3,
                         cudaFuncAttributePreferredSharedMemoryCarveout, 100);

    init_kernel<<<16, 256>>>(targets, init_tok, hidden);

    // W_out fp16 conversion (PDL primary) overlapped with x_gates GEMM
    conv_w<<<256, 256>>>(W_out);
    {
        cudaLaunchConfig_t cfg = {};
        cfg.gridDim  = dim3(NGATE / 128, NTOK / 128);
        cfg.blockDim = dim3(256);
        cudaLaunchAttribute attr[1];
        attr[0].id = cudaLaunchAttributeProgrammaticStreamSerialization;
        attr[0].val.programmaticStreamSerializationAllowed = 1;
        cfg.attrs = attr;
        cfg.numAttrs = 1;
        cudaLaunchKernelEx(&cfg, gemm_xg, (const float*)embedding,
                           (const float*)W_ih, (const float*)b_ih);
    }

    // sequential GRU scan (persistent, 128 co-resident CTAs)
    recur_kernel<<<128, 256, RS_TOT>>>(W_hh, b_hh);

    // logits GEMM (fp16, 4-stage), PDL-overlapped with the scan
    {
        cudaLaunchConfig_t cfg = {};
        cfg.gridDim  = dim3(VOC / 128, NTOK / 128);
        cfg.blockDim = dim3(256);
        cfg.dynamicSmemBytes = SMEMH;
        cudaLaunchAttribute attr[1];
        attr[0].id = cudaLaunchAttributeProgrammaticStreamSerialization;
        attr[0].val.programmaticStreamSerializationAllowed = 1;
        cfg.attrs = attr;
        cfg.numAttrs = 1;
        cudaLaunchKernelEx(&cfg, gemm3, (const float*)b_out, out);
    }
}